// round 7
// baseline (speedup 1.0000x reference)
#include <cuda_runtime.h>
#include <cuda_bf16.h>
#include <math.h>
#include <stdint.h>

#define N_TOK 8192
#define DIM   1024
#define HID   4096
#define NE    8
#define STRD  12

// dynamic smem layout (bytes)
#define OFF_A    0          // [2buf][2hl][128][12] u32 = 24576
#define OFF_B    24576      // [2buf][2hl][256][12] u32 = 49152
#define OFF_AROW 73728      // 128 u32
#define OFF_BROW 74240      // 256 u32
#define SMEM_TOTAL 75264

// ======================= PTX helpers =======================
__device__ __forceinline__ uint32_t smem_u32(const void* p) {
    uint32_t a;
    asm("{ .reg .u64 t; cvta.to.shared.u64 t, %1; cvt.u32.u64 %0, t; }" : "=r"(a) : "l"(p));
    return a;
}
#define CPA16(s, g) asm volatile("cp.async.cg.shared.global [%0], [%1], 16;" :: "r"(s), "l"(g))
#define CPC()       asm volatile("cp.async.commit_group;" ::: "memory")
#define CPW(n)      asm volatile("cp.async.wait_group %0;" :: "n"(n) : "memory")

__device__ __forceinline__ void mma_bf16(float* d, const uint32_t* a, const uint32_t* b) {
    asm volatile("mma.sync.aligned.m16n8k16.row.col.f32.bf16.bf16.f32 "
                 "{%0,%1,%2,%3},{%4,%5,%6,%7},{%8,%9},{%0,%1,%2,%3};"
                 : "+f"(d[0]), "+f"(d[1]), "+f"(d[2]), "+f"(d[3])
                 : "r"(a[0]), "r"(a[1]), "r"(a[2]), "r"(a[3]), "r"(b[0]), "r"(b[1]));
}

// ======================= device scratch =======================
__device__ int   g_count[NE];
__device__ int   g_off[NE];
__device__ int   g_tok[NE * N_TOK];
__device__ float g_gate[NE * N_TOK];
__device__ float g_ent;
__device__ float g_imp[NE];

__device__ __align__(16) __nv_bfloat16 g_xh[(size_t)N_TOK * DIM];
__device__ __align__(16) __nv_bfloat16 g_xl[(size_t)N_TOK * DIM];
__device__ __align__(16) __nv_bfloat16 g_w1h[(size_t)NE * HID * DIM];   // [e][n(hid)][k(dim)]
__device__ __align__(16) __nv_bfloat16 g_w1l[(size_t)NE * HID * DIM];
__device__ __align__(16) __nv_bfloat16 g_w2h[(size_t)NE * DIM * HID];   // [e][n(dim)][k(hid)]
__device__ __align__(16) __nv_bfloat16 g_w2l[(size_t)NE * DIM * HID];
__device__ __align__(16) __nv_bfloat16 g_hh[(size_t)2 * N_TOK * HID];   // [slot][hid]
__device__ __align__(16) __nv_bfloat16 g_hl[(size_t)2 * N_TOK * HID];

// ======================= small kernels =======================
__global__ void zero_kernel() {
    int t = threadIdx.x;
    if (t < NE) { g_count[t] = 0; g_imp[t] = 0.f; }
    if (t == 0) g_ent = 0.f;
}

__global__ void router_kernel(const float* __restrict__ x,
                              const float* __restrict__ rw,
                              const float* __restrict__ rb) {
    __shared__ float s_ent[8];
    __shared__ float s_imp[8][NE];
    int warp = threadIdx.x >> 5;
    int lane = threadIdx.x & 31;
    int t = blockIdx.x * 8 + warp;

    float acc[NE];
#pragma unroll
    for (int e = 0; e < NE; e++) acc[e] = 0.f;
    const float* xr = x + (size_t)t * DIM;
    for (int k = lane; k < DIM; k += 32) {
        float xv = xr[k];
        const float* rwk = rw + k * NE;
#pragma unroll
        for (int e = 0; e < NE; e++) acc[e] += xv * rwk[e];
    }
#pragma unroll
    for (int e = 0; e < NE; e++)
#pragma unroll
        for (int s = 16; s > 0; s >>= 1)
            acc[e] += __shfl_xor_sync(0xffffffff, acc[e], s);

    if (lane == 0) {
        float lg[NE], m = -1e30f;
#pragma unroll
        for (int e = 0; e < NE; e++) { lg[e] = acc[e] + rb[e]; m = fmaxf(m, lg[e]); }
        float p[NE], sum = 0.f;
#pragma unroll
        for (int e = 0; e < NE; e++) { p[e] = expf(lg[e] - m); sum += p[e]; }
        float inv = 1.f / sum, ent = 0.f;
#pragma unroll
        for (int e = 0; e < NE; e++) {
            float pe = p[e] * inv;
            ent -= pe * logf(fmaxf(pe, 1e-8f));
            s_imp[warp][e] = pe;
        }
        s_ent[warp] = ent;
        int e0 = 0;
#pragma unroll
        for (int e = 1; e < NE; e++) if (lg[e] > lg[e0]) e0 = e;
        int e1 = (e0 == 0) ? 1 : 0;
#pragma unroll
        for (int e = 0; e < NE; e++) if (e != e0 && lg[e] > lg[e1]) e1 = e;
        float g0 = 1.f / (1.f + expf(lg[e1] - lg[e0]));
        float g1 = 1.f - g0;
        int p0 = atomicAdd(&g_count[e0], 1);
        g_tok [e0 * N_TOK + p0] = t; g_gate[e0 * N_TOK + p0] = g0;
        int p1 = atomicAdd(&g_count[e1], 1);
        g_tok [e1 * N_TOK + p1] = t; g_gate[e1 * N_TOK + p1] = g1;
    }
    __syncthreads();
    if (threadIdx.x < NE) {
        float se = 0.f;
#pragma unroll
        for (int w = 0; w < 8; w++) se += s_imp[w][threadIdx.x];
        atomicAdd(&g_imp[threadIdx.x], se);
    }
    if (threadIdx.x == 0) {
        float se = 0.f;
#pragma unroll
        for (int w = 0; w < 8; w++) se += s_ent[w];
        atomicAdd(&g_ent, se);
    }
}

__global__ void offsets_kernel() {
    if (threadIdx.x == 0) {
        int s = 0;
#pragma unroll
        for (int e = 0; e < NE; e++) { g_off[e] = s; s += g_count[e]; }
    }
}

__global__ void convert_x_kernel(const float* __restrict__ x) {
    size_t i = ((size_t)blockIdx.x * 256 + threadIdx.x) * 4;
    float4 v = *(const float4*)(x + i);
    float f[4] = {v.x, v.y, v.z, v.w};
    uint32_t ph[2], pl[2];
#pragma unroll
    for (int j = 0; j < 2; j++) {
        __nv_bfloat16 h0 = __float2bfloat16(f[2*j]),   h1 = __float2bfloat16(f[2*j+1]);
        __nv_bfloat16 l0 = __float2bfloat16(f[2*j]   - __bfloat162float(h0));
        __nv_bfloat16 l1 = __float2bfloat16(f[2*j+1] - __bfloat162float(h1));
        ph[j] = (uint32_t)__bfloat16_as_ushort(h0) | ((uint32_t)__bfloat16_as_ushort(h1) << 16);
        pl[j] = (uint32_t)__bfloat16_as_ushort(l0) | ((uint32_t)__bfloat16_as_ushort(l1) << 16);
    }
    *(uint2*)(g_xh + i) = make_uint2(ph[0], ph[1]);
    *(uint2*)(g_xl + i) = make_uint2(pl[0], pl[1]);
}

// transpose+split: src [e][R][C] fp32 -> INTERNAL dst [e][C][R] bf16 hi/lo
// which=0 -> g_w1h/g_w1l ; which=1 -> g_w2h/g_w2l   (never pass device globals as args)
__global__ void transpose_convert_kernel(const float* __restrict__ src,
                                         int which, int R, int C) {
    __shared__ float t[32][33];
    __nv_bfloat16* dh = which ? g_w2h : g_w1h;
    __nv_bfloat16* dl = which ? g_w2l : g_w1l;
    int e = blockIdx.z;
    int c0 = blockIdx.x * 32, r0 = blockIdx.y * 32;
    const float* s = src + (size_t)e * R * C;
#pragma unroll
    for (int i = threadIdx.y; i < 32; i += 8)
        t[i][threadIdx.x] = s[(size_t)(r0 + i) * C + c0 + threadIdx.x];
    __syncthreads();
#pragma unroll
    for (int i = threadIdx.y; i < 32; i += 8) {
        float v = t[threadIdx.x][i];
        __nv_bfloat16 h = __float2bfloat16(v);
        __nv_bfloat16 l = __float2bfloat16(v - __bfloat162float(h));
        size_t o = (size_t)e * R * C + (size_t)(c0 + i) * R + r0 + threadIdx.x;
        dh[o] = h; dl[o] = l;
    }
}

// ======================= cp.async stage loader =======================
// A tile 128 rows, B tile 256 rows, K-chunk 16 (32B), hi+lo.
__device__ __forceinline__ void load_stage(
    uint32_t sbase,
    const __nv_bfloat16* __restrict__ Ah, const __nv_bfloat16* __restrict__ Al,
    const __nv_bfloat16* __restrict__ Bh, const __nv_bfloat16* __restrict__ Bl,
    const uint32_t* __restrict__ arow, const uint32_t* __restrict__ brow,
    int k0, int buf)
{
    int tid = threadIdx.x;
    int row = tid >> 1, half = tid & 1;
    uint32_t hb = (uint32_t)half * 16u;

    uint32_t ka = arow[row] + k0 + half * 8;
    uint32_t da = sbase + OFF_A + (uint32_t)(buf * 2) * (128 * 48) + (uint32_t)row * 48 + hb;
    CPA16(da,            Ah + ka);
    CPA16(da + 128 * 48, Al + ka);

    uint32_t kb0 = brow[row]       + k0 + half * 8;
    uint32_t kb1 = brow[row + 128] + k0 + half * 8;
    uint32_t db = sbase + OFF_B + (uint32_t)(buf * 2) * (256 * 48) + (uint32_t)row * 48 + hb;
    CPA16(db,                  Bh + kb0);
    CPA16(db + 128 * 48,       Bh + kb1);
    CPA16(db + 256 * 48,       Bl + kb0);
    CPA16(db + 256 * 48 + 128 * 48, Bl + kb1);
    CPC();
}

// ======================= GEMM mainloop: CTA 128x256, warp 64x64 =======================
__device__ __forceinline__ void mma_mainloop(
    uint32_t sbase, char* smc,
    const __nv_bfloat16* __restrict__ Ah, const __nv_bfloat16* __restrict__ Al,
    const __nv_bfloat16* __restrict__ Bh, const __nv_bfloat16* __restrict__ Bl,
    const uint32_t* __restrict__ arow, const uint32_t* __restrict__ brow,
    int S, float (&acc)[4][8][4])
{
    int tid  = threadIdx.x;
    int lane = tid & 31;
    int wid  = tid >> 5;
    int wm   = wid & 1;        // 2 m-groups of 64
    int wn   = wid >> 1;       // 4 n-groups of 64
    int q    = lane & 3;
    int r4   = lane >> 2;

    uint32_t (*A)[128][STRD] = (uint32_t (*)[128][STRD])(smc + OFF_A);  // [buf*2+h]
    uint32_t (*B)[256][STRD] = (uint32_t (*)[256][STRD])(smc + OFF_B);

    load_stage(sbase, Ah, Al, Bh, Bl, arow, brow, 0, 0);

    for (int s = 0; s < S; s++) {
        if (s + 1 < S) {
            load_stage(sbase, Ah, Al, Bh, Bl, arow, brow, (s + 1) * 16, (s + 1) & 1);
            CPW(1);
        } else {
            CPW(0);
        }
        __syncthreads();

        int bf = (s & 1) * 2;
        uint32_t bhf[8][2], blf[8][2];
#pragma unroll
        for (int nt = 0; nt < 8; nt++) {
            int nb = wn * 64 + nt * 8 + r4;
            bhf[nt][0] = B[bf][nb][q];     bhf[nt][1] = B[bf][nb][4 + q];
            blf[nt][0] = B[bf + 1][nb][q]; blf[nt][1] = B[bf + 1][nb][4 + q];
        }
#pragma unroll
        for (int mt = 0; mt < 4; mt++) {
            int ra = wm * 64 + mt * 16 + r4;
            uint32_t ah[4], al[4];
            ah[0] = A[bf][ra][q];          ah[1] = A[bf][ra + 8][q];
            ah[2] = A[bf][ra][4 + q];      ah[3] = A[bf][ra + 8][4 + q];
            al[0] = A[bf + 1][ra][q];      al[1] = A[bf + 1][ra + 8][q];
            al[2] = A[bf + 1][ra][4 + q];  al[3] = A[bf + 1][ra + 8][4 + q];
#pragma unroll
            for (int nt = 0; nt < 8; nt++) {
                mma_bf16(acc[mt][nt], ah, bhf[nt]);
                mma_bf16(acc[mt][nt], al, bhf[nt]);
                mma_bf16(acc[mt][nt], ah, blf[nt]);
            }
        }
        __syncthreads();   // all reads of buf[s&1] done before iter s+1 overwrites it
    }
}

// ======================= GEMM1: h = relu(x @ w1 + b1) =======================
__global__ void __launch_bounds__(256)
gemm1_mma(const float* __restrict__ b1) {
    int e = blockIdx.z;
    int ce = g_count[e];
    int m0 = blockIdx.y * 128;
    if (m0 >= ce) return;
    int n0 = blockIdx.x * 256;
    int off = g_off[e];

    extern __shared__ char smc[];
    uint32_t sbase = smem_u32(smc);
    uint32_t* s_arow = (uint32_t*)(smc + OFF_AROW);
    uint32_t* s_brow = (uint32_t*)(smc + OFF_BROW);

    int tid = threadIdx.x;
    if (tid < 128) {
        int tok = (m0 + tid < ce) ? g_tok[e * N_TOK + m0 + tid] : 0;
        s_arow[tid] = (uint32_t)tok * DIM;
    }
    s_brow[tid] = (uint32_t)(e * HID + n0 + tid) * DIM;
    __syncthreads();

    float acc[4][8][4];
#pragma unroll
    for (int i = 0; i < 4; i++)
#pragma unroll
        for (int j = 0; j < 8; j++)
#pragma unroll
            for (int k = 0; k < 4; k++) acc[i][j][k] = 0.f;

    mma_mainloop(sbase, smc, g_xh, g_xl, g_w1h, g_w1l, s_arow, s_brow, DIM / 16, acc);

    int lane = tid & 31, wid = tid >> 5;
    int wm = wid & 1, wn = wid >> 1;
    int r = lane >> 2, q = lane & 3;
#pragma unroll
    for (int mt = 0; mt < 4; mt++) {
#pragma unroll
        for (int rh = 0; rh < 2; rh++) {
            int row = wm * 64 + mt * 16 + r + rh * 8;
            if (m0 + row >= ce) continue;
            size_t slot = (size_t)(off + m0 + row);
#pragma unroll
            for (int nt = 0; nt < 8; nt++) {
                int col = n0 + wn * 64 + nt * 8 + 2 * q;
                float f0 = acc[mt][nt][rh * 2 + 0] + b1[e * HID + col];
                float f1 = acc[mt][nt][rh * 2 + 1] + b1[e * HID + col + 1];
                f0 = fmaxf(f0, 0.f); f1 = fmaxf(f1, 0.f);
                __nv_bfloat16 h0 = __float2bfloat16(f0), h1 = __float2bfloat16(f1);
                __nv_bfloat16 l0 = __float2bfloat16(f0 - __bfloat162float(h0));
                __nv_bfloat16 l1 = __float2bfloat16(f1 - __bfloat162float(h1));
                uint32_t ph = (uint32_t)__bfloat16_as_ushort(h0) | ((uint32_t)__bfloat16_as_ushort(h1) << 16);
                uint32_t pl = (uint32_t)__bfloat16_as_ushort(l0) | ((uint32_t)__bfloat16_as_ushort(l1) << 16);
                *(uint32_t*)(g_hh + slot * HID + col) = ph;
                *(uint32_t*)(g_hl + slot * HID + col) = pl;
            }
        }
    }
}

// ======================= GEMM2: out += gate * (h @ w2 + b2) =======================
__global__ void __launch_bounds__(256)
gemm2_mma(const float* __restrict__ b2, float* __restrict__ out) {
    int e = blockIdx.z;
    int ce = g_count[e];
    int m0 = blockIdx.y * 128;
    if (m0 >= ce) return;
    int n0 = blockIdx.x * 256;
    int off = g_off[e];

    extern __shared__ char smc[];
    uint32_t sbase = smem_u32(smc);
    uint32_t* s_arow = (uint32_t*)(smc + OFF_AROW);
    uint32_t* s_brow = (uint32_t*)(smc + OFF_BROW);

    int tid = threadIdx.x;
    if (tid < 128) {
        int sl = off + m0 + tid;
        if (sl > 2 * N_TOK - 1) sl = 2 * N_TOK - 1;
        s_arow[tid] = (uint32_t)sl * HID;
    }
    s_brow[tid] = (uint32_t)(e * DIM + n0 + tid) * HID;
    __syncthreads();

    float acc[4][8][4];
#pragma unroll
    for (int i = 0; i < 4; i++)
#pragma unroll
        for (int j = 0; j < 8; j++)
#pragma unroll
            for (int k = 0; k < 4; k++) acc[i][j][k] = 0.f;

    mma_mainloop(sbase, smc, g_hh, g_hl, g_w2h, g_w2l, s_arow, s_brow, HID / 16, acc);

    int lane = tid & 31, wid = tid >> 5;
    int wm = wid & 1, wn = wid >> 1;
    int r = lane >> 2, q = lane & 3;
#pragma unroll
    for (int mt = 0; mt < 4; mt++) {
#pragma unroll
        for (int rh = 0; rh < 2; rh++) {
            int row = wm * 64 + mt * 16 + r + rh * 8;
            if (m0 + row >= ce) continue;
            int slot2 = e * N_TOK + m0 + row;
            int tok = g_tok[slot2];
            float gw = g_gate[slot2];
            float* ob = out + (size_t)tok * DIM;
#pragma unroll
            for (int nt = 0; nt < 8; nt++) {
                int col = n0 + wn * 64 + nt * 8 + 2 * q;
                float f0 = acc[mt][nt][rh * 2 + 0] + b2[e * DIM + col];
                float f1 = acc[mt][nt][rh * 2 + 1] + b2[e * DIM + col + 1];
                atomicAdd(ob + col,     gw * f0);
                atomicAdd(ob + col + 1, gw * f1);
            }
        }
    }
}

// ======================= aux =======================
__global__ void aux_kernel(float* __restrict__ out, int out_size) {
    if (threadIdx.x == 0 && out_size >= N_TOK * DIM + 2) {
        float ent = g_ent / (float)N_TOK;
        float lb = 0.f;
#pragma unroll
        for (int e = 0; e < NE; e++) {
            float d = g_imp[e] / (float)N_TOK - 1.f / (float)NE;
            lb += d * d;
        }
        lb /= (float)NE;
        out[N_TOK * DIM]     = ent;
        out[N_TOK * DIM + 1] = lb;
    }
}

// ======================= launch =======================
extern "C" void kernel_launch(void* const* d_in, const int* in_sizes, int n_in,
                              void* d_out, int out_size) {
    const float* x  = (const float*)d_in[0];
    const float* rw = (const float*)d_in[1];
    const float* rb = (const float*)d_in[2];
    const float* w1 = (const float*)d_in[3];
    const float* b1 = (const float*)d_in[4];
    const float* w2 = (const float*)d_in[5];
    const float* b2 = (const float*)d_in[6];
    float* out = (float*)d_out;

    cudaFuncSetAttribute(gemm1_mma, cudaFuncAttributeMaxDynamicSharedMemorySize, SMEM_TOTAL);
    cudaFuncSetAttribute(gemm2_mma, cudaFuncAttributeMaxDynamicSharedMemorySize, SMEM_TOTAL);

    cudaMemsetAsync(d_out, 0, (size_t)out_size * sizeof(float), 0);
    zero_kernel<<<1, 32>>>();
    router_kernel<<<N_TOK / 8, 256>>>(x, rw, rb);
    offsets_kernel<<<1, 1>>>();

    convert_x_kernel<<<(N_TOK * DIM) / 1024, 256>>>(x);
    {
        dim3 g(HID / 32, DIM / 32, NE), b(32, 8);
        transpose_convert_kernel<<<g, b>>>(w1, 0, DIM, HID);
    }
    {
        dim3 g(DIM / 32, HID / 32, NE), b(32, 8);
        transpose_convert_kernel<<<g, b>>>(w2, 1, HID, DIM);
    }

    {
        dim3 g(HID / 256, N_TOK / 128, NE);
        gemm1_mma<<<g, 256, SMEM_TOTAL>>>(b1);
    }
    {
        dim3 g(DIM / 256, N_TOK / 128, NE);
        gemm2_mma<<<g, 256, SMEM_TOTAL>>>(b2, out);
    }
    aux_kernel<<<1, 1>>>(out, out_size);
}

// round 8
// speedup vs baseline: 1.3875x; 1.3875x over previous
#include <cuda_runtime.h>
#include <cuda_fp16.h>
#include <math.h>
#include <stdint.h>

#define N_TOK 8192
#define DIM   1024
#define HID   4096
#define NE    8
#define STRD  12

// dynamic smem layout (bytes)
#define OFF_A    0          // [2buf][2hl][128][12] u32 = 24576
#define OFF_B    24576      // [2buf][256][12] u32     = 24576
#define OFF_AROW 49152      // 128 u32
#define OFF_BROW 49664      // 256 u32
#define SMEM_TOTAL 50688

// ======================= PTX helpers =======================
__device__ __forceinline__ uint32_t smem_u32(const void* p) {
    uint32_t a;
    asm("{ .reg .u64 t; cvta.to.shared.u64 t, %1; cvt.u32.u64 %0, t; }" : "=r"(a) : "l"(p));
    return a;
}
#define CPA16(s, g) asm volatile("cp.async.cg.shared.global [%0], [%1], 16;" :: "r"(s), "l"(g))
#define CPC()       asm volatile("cp.async.commit_group;" ::: "memory")
#define CPW(n)      asm volatile("cp.async.wait_group %0;" :: "n"(n) : "memory")

__device__ __forceinline__ void mma_f16(float* d, const uint32_t* a, const uint32_t* b) {
    asm volatile("mma.sync.aligned.m16n8k16.row.col.f32.f16.f16.f32 "
                 "{%0,%1,%2,%3},{%4,%5,%6,%7},{%8,%9},{%0,%1,%2,%3};"
                 : "+f"(d[0]), "+f"(d[1]), "+f"(d[2]), "+f"(d[3])
                 : "r"(a[0]), "r"(a[1]), "r"(a[2]), "r"(a[3]), "r"(b[0]), "r"(b[1]));
}

// ======================= device scratch =======================
__device__ int   g_count[NE];
__device__ int   g_off[NE];
__device__ int   g_tok[NE * N_TOK];
__device__ float g_gate[NE * N_TOK];
__device__ float g_ent;
__device__ float g_imp[NE];

__device__ __align__(16) __half g_xh[(size_t)N_TOK * DIM];
__device__ __align__(16) __half g_xl[(size_t)N_TOK * DIM];
__device__ __align__(16) __half g_w1h[(size_t)NE * HID * DIM];   // [e][n(hid)][k(dim)]
__device__ __align__(16) __half g_w2h[(size_t)NE * DIM * HID];   // [e][n(dim)][k(hid)]
__device__ __align__(16) __half g_hh[(size_t)2 * N_TOK * HID];   // [slot][hid]
__device__ __align__(16) __half g_hl[(size_t)2 * N_TOK * HID];

// ======================= small kernels =======================
__global__ void zero_kernel() {
    int t = threadIdx.x;
    if (t < NE) { g_count[t] = 0; g_imp[t] = 0.f; }
    if (t == 0) g_ent = 0.f;
}

__global__ void router_kernel(const float* __restrict__ x,
                              const float* __restrict__ rw,
                              const float* __restrict__ rb) {
    __shared__ float s_ent[8];
    __shared__ float s_imp[8][NE];
    int warp = threadIdx.x >> 5;
    int lane = threadIdx.x & 31;
    int t = blockIdx.x * 8 + warp;

    float acc[NE];
#pragma unroll
    for (int e = 0; e < NE; e++) acc[e] = 0.f;
    const float* xr = x + (size_t)t * DIM;
    for (int k = lane; k < DIM; k += 32) {
        float xv = xr[k];
        const float* rwk = rw + k * NE;
#pragma unroll
        for (int e = 0; e < NE; e++) acc[e] += xv * rwk[e];
    }
#pragma unroll
    for (int e = 0; e < NE; e++)
#pragma unroll
        for (int s = 16; s > 0; s >>= 1)
            acc[e] += __shfl_xor_sync(0xffffffff, acc[e], s);

    if (lane == 0) {
        float lg[NE], m = -1e30f;
#pragma unroll
        for (int e = 0; e < NE; e++) { lg[e] = acc[e] + rb[e]; m = fmaxf(m, lg[e]); }
        float p[NE], sum = 0.f;
#pragma unroll
        for (int e = 0; e < NE; e++) { p[e] = expf(lg[e] - m); sum += p[e]; }
        float inv = 1.f / sum, ent = 0.f;
#pragma unroll
        for (int e = 0; e < NE; e++) {
            float pe = p[e] * inv;
            ent -= pe * logf(fmaxf(pe, 1e-8f));
            s_imp[warp][e] = pe;
        }
        s_ent[warp] = ent;
        int e0 = 0;
#pragma unroll
        for (int e = 1; e < NE; e++) if (lg[e] > lg[e0]) e0 = e;
        int e1 = (e0 == 0) ? 1 : 0;
#pragma unroll
        for (int e = 0; e < NE; e++) if (e != e0 && lg[e] > lg[e1]) e1 = e;
        float g0 = 1.f / (1.f + expf(lg[e1] - lg[e0]));
        float g1 = 1.f - g0;
        int p0 = atomicAdd(&g_count[e0], 1);
        g_tok [e0 * N_TOK + p0] = t; g_gate[e0 * N_TOK + p0] = g0;
        int p1 = atomicAdd(&g_count[e1], 1);
        g_tok [e1 * N_TOK + p1] = t; g_gate[e1 * N_TOK + p1] = g1;
    }
    __syncthreads();
    if (threadIdx.x < NE) {
        float se = 0.f;
#pragma unroll
        for (int w = 0; w < 8; w++) se += s_imp[w][threadIdx.x];
        atomicAdd(&g_imp[threadIdx.x], se);
    }
    if (threadIdx.x == 0) {
        float se = 0.f;
#pragma unroll
        for (int w = 0; w < 8; w++) se += s_ent[w];
        atomicAdd(&g_ent, se);
    }
}

__global__ void offsets_kernel() {
    if (threadIdx.x == 0) {
        int s = 0;
#pragma unroll
        for (int e = 0; e < NE; e++) { g_off[e] = s; s += g_count[e]; }
    }
}

__global__ void convert_x_kernel(const float* __restrict__ x) {
    size_t i = ((size_t)blockIdx.x * 256 + threadIdx.x) * 4;
    float4 v = *(const float4*)(x + i);
    float f[4] = {v.x, v.y, v.z, v.w};
    uint32_t ph[2], pl[2];
#pragma unroll
    for (int j = 0; j < 2; j++) {
        __half h0 = __float2half_rn(f[2*j]),   h1 = __float2half_rn(f[2*j+1]);
        __half l0 = __float2half_rn(f[2*j]   - __half2float(h0));
        __half l1 = __float2half_rn(f[2*j+1] - __half2float(h1));
        ph[j] = (uint32_t)__half_as_ushort(h0) | ((uint32_t)__half_as_ushort(h1) << 16);
        pl[j] = (uint32_t)__half_as_ushort(l0) | ((uint32_t)__half_as_ushort(l1) << 16);
    }
    *(uint2*)(g_xh + i) = make_uint2(ph[0], ph[1]);
    *(uint2*)(g_xl + i) = make_uint2(pl[0], pl[1]);
}

// transpose: src [e][R][C] fp32 -> INTERNAL dst [e][C][R] fp16 (hi only)
// which=0 -> g_w1h ; which=1 -> g_w2h   (never pass device globals as host args)
__global__ void transpose_convert_kernel(const float* __restrict__ src,
                                         int which, int R, int C) {
    __shared__ float t[32][33];
    __half* dh = which ? g_w2h : g_w1h;
    int e = blockIdx.z;
    int c0 = blockIdx.x * 32, r0 = blockIdx.y * 32;
    const float* s = src + (size_t)e * R * C;
#pragma unroll
    for (int i = threadIdx.y; i < 32; i += 8)
        t[i][threadIdx.x] = s[(size_t)(r0 + i) * C + c0 + threadIdx.x];
    __syncthreads();
#pragma unroll
    for (int i = threadIdx.y; i < 32; i += 8) {
        float v = t[threadIdx.x][i];
        size_t o = (size_t)e * R * C + (size_t)(c0 + i) * R + r0 + threadIdx.x;
        dh[o] = __float2half_rn(v);
    }
}

// ======================= cp.async stage loader =======================
// A tile 128 rows (hi+lo), B tile 256 rows (hi only), K-chunk 16 (32B).
__device__ __forceinline__ void load_stage(
    uint32_t sbase,
    const __half* __restrict__ Ah, const __half* __restrict__ Al,
    const __half* __restrict__ Bh,
    const uint32_t* __restrict__ arow, const uint32_t* __restrict__ brow,
    int k0, int buf)
{
    int tid = threadIdx.x;
    int row = tid >> 1, half = tid & 1;
    uint32_t hb = (uint32_t)half * 16u;

    uint32_t ka = arow[row] + k0 + half * 8;
    uint32_t da = sbase + OFF_A + (uint32_t)(buf * 2) * (128 * 48) + (uint32_t)row * 48 + hb;
    CPA16(da,            Ah + ka);
    CPA16(da + 128 * 48, Al + ka);

    uint32_t kb0 = brow[row]       + k0 + half * 8;
    uint32_t kb1 = brow[row + 128] + k0 + half * 8;
    uint32_t db = sbase + OFF_B + (uint32_t)buf * (256 * 48) + (uint32_t)row * 48 + hb;
    CPA16(db,            Bh + kb0);
    CPA16(db + 128 * 48, Bh + kb1);
    CPC();
}

// ======================= GEMM mainloop: CTA 128x256, warp 64x64, 2-term fp16 =======================
__device__ __forceinline__ void mma_mainloop(
    uint32_t sbase, char* smc,
    const __half* __restrict__ Ah, const __half* __restrict__ Al,
    const __half* __restrict__ Bh,
    const uint32_t* __restrict__ arow, const uint32_t* __restrict__ brow,
    int S, float (&acc)[4][8][4])
{
    int tid  = threadIdx.x;
    int lane = tid & 31;
    int wid  = tid >> 5;
    int wm   = wid & 1;        // 2 m-groups of 64
    int wn   = wid >> 1;       // 4 n-groups of 64
    int q    = lane & 3;
    int r4   = lane >> 2;

    uint32_t (*A)[128][STRD] = (uint32_t (*)[128][STRD])(smc + OFF_A);  // [buf*2+hl]
    uint32_t (*B)[256][STRD] = (uint32_t (*)[256][STRD])(smc + OFF_B);  // [buf]

    load_stage(sbase, Ah, Al, Bh, arow, brow, 0, 0);

    for (int s = 0; s < S; s++) {
        if (s + 1 < S) {
            load_stage(sbase, Ah, Al, Bh, arow, brow, (s + 1) * 16, (s + 1) & 1);
            CPW(1);
        } else {
            CPW(0);
        }
        __syncthreads();

        int bu = s & 1;
        int bf = bu * 2;
        uint32_t bhf[8][2];
#pragma unroll
        for (int nt = 0; nt < 8; nt++) {
            int nb = wn * 64 + nt * 8 + r4;
            bhf[nt][0] = B[bu][nb][q];
            bhf[nt][1] = B[bu][nb][4 + q];
        }
#pragma unroll
        for (int mt = 0; mt < 4; mt++) {
            int ra = wm * 64 + mt * 16 + r4;
            uint32_t ah[4], al[4];
            ah[0] = A[bf][ra][q];          ah[1] = A[bf][ra + 8][q];
            ah[2] = A[bf][ra][4 + q];      ah[3] = A[bf][ra + 8][4 + q];
            al[0] = A[bf + 1][ra][q];      al[1] = A[bf + 1][ra + 8][q];
            al[2] = A[bf + 1][ra][4 + q];  al[3] = A[bf + 1][ra + 8][4 + q];
#pragma unroll
            for (int nt = 0; nt < 8; nt++) {
                mma_f16(acc[mt][nt], ah, bhf[nt]);
                mma_f16(acc[mt][nt], al, bhf[nt]);
            }
        }
        __syncthreads();   // reads of buf done before next iter overwrites it
    }
}

// ======================= GEMM1: h = relu(x @ w1 + b1) =======================
__global__ void __launch_bounds__(256)
gemm1_mma(const float* __restrict__ b1) {
    int e = blockIdx.z;
    int ce = g_count[e];
    int m0 = blockIdx.y * 128;
    if (m0 >= ce) return;
    int n0 = blockIdx.x * 256;
    int off = g_off[e];

    extern __shared__ char smc[];
    uint32_t sbase = smem_u32(smc);
    uint32_t* s_arow = (uint32_t*)(smc + OFF_AROW);
    uint32_t* s_brow = (uint32_t*)(smc + OFF_BROW);

    int tid = threadIdx.x;
    if (tid < 128) {
        int tok = (m0 + tid < ce) ? g_tok[e * N_TOK + m0 + tid] : 0;
        s_arow[tid] = (uint32_t)tok * DIM;
    }
    s_brow[tid] = (uint32_t)(e * HID + n0 + tid) * DIM;
    __syncthreads();

    float acc[4][8][4];
#pragma unroll
    for (int i = 0; i < 4; i++)
#pragma unroll
        for (int j = 0; j < 8; j++)
#pragma unroll
            for (int k = 0; k < 4; k++) acc[i][j][k] = 0.f;

    mma_mainloop(sbase, smc, g_xh, g_xl, g_w1h, s_arow, s_brow, DIM / 16, acc);

    int lane = tid & 31, wid = tid >> 5;
    int wm = wid & 1, wn = wid >> 1;
    int r = lane >> 2, q = lane & 3;
#pragma unroll
    for (int mt = 0; mt < 4; mt++) {
#pragma unroll
        for (int rh = 0; rh < 2; rh++) {
            int row = wm * 64 + mt * 16 + r + rh * 8;
            if (m0 + row >= ce) continue;
            size_t slot = (size_t)(off + m0 + row);
#pragma unroll
            for (int nt = 0; nt < 8; nt++) {
                int col = n0 + wn * 64 + nt * 8 + 2 * q;
                float f0 = acc[mt][nt][rh * 2 + 0] + b1[e * HID + col];
                float f1 = acc[mt][nt][rh * 2 + 1] + b1[e * HID + col + 1];
                f0 = fmaxf(f0, 0.f); f1 = fmaxf(f1, 0.f);
                __half h0 = __float2half_rn(f0), h1 = __float2half_rn(f1);
                __half l0 = __float2half_rn(f0 - __half2float(h0));
                __half l1 = __float2half_rn(f1 - __half2float(h1));
                uint32_t ph = (uint32_t)__half_as_ushort(h0) | ((uint32_t)__half_as_ushort(h1) << 16);
                uint32_t pl = (uint32_t)__half_as_ushort(l0) | ((uint32_t)__half_as_ushort(l1) << 16);
                *(uint32_t*)(g_hh + slot * HID + col) = ph;
                *(uint32_t*)(g_hl + slot * HID + col) = pl;
            }
        }
    }
}

// ======================= GEMM2: out += gate * (h @ w2 + b2) =======================
__global__ void __launch_bounds__(256)
gemm2_mma(const float* __restrict__ b2, float* __restrict__ out) {
    int e = blockIdx.z;
    int ce = g_count[e];
    int m0 = blockIdx.y * 128;
    if (m0 >= ce) return;
    int n0 = blockIdx.x * 256;
    int off = g_off[e];

    extern __shared__ char smc[];
    uint32_t sbase = smem_u32(smc);
    uint32_t* s_arow = (uint32_t*)(smc + OFF_AROW);
    uint32_t* s_brow = (uint32_t*)(smc + OFF_BROW);

    int tid = threadIdx.x;
    if (tid < 128) {
        int sl = off + m0 + tid;
        if (sl > 2 * N_TOK - 1) sl = 2 * N_TOK - 1;
        s_arow[tid] = (uint32_t)sl * HID;
    }
    s_brow[tid] = (uint32_t)(e * DIM + n0 + tid) * HID;
    __syncthreads();

    float acc[4][8][4];
#pragma unroll
    for (int i = 0; i < 4; i++)
#pragma unroll
        for (int j = 0; j < 8; j++)
#pragma unroll
            for (int k = 0; k < 4; k++) acc[i][j][k] = 0.f;

    mma_mainloop(sbase, smc, g_hh, g_hl, g_w2h, s_arow, s_brow, HID / 16, acc);

    int lane = tid & 31, wid = tid >> 5;
    int wm = wid & 1, wn = wid >> 1;
    int r = lane >> 2, q = lane & 3;
#pragma unroll
    for (int mt = 0; mt < 4; mt++) {
#pragma unroll
        for (int rh = 0; rh < 2; rh++) {
            int row = wm * 64 + mt * 16 + r + rh * 8;
            if (m0 + row >= ce) continue;
            int slot2 = e * N_TOK + m0 + row;
            int tok = g_tok[slot2];
            float gw = g_gate[slot2];
            float* ob = out + (size_t)tok * DIM;
#pragma unroll
            for (int nt = 0; nt < 8; nt++) {
                int col = n0 + wn * 64 + nt * 8 + 2 * q;
                float f0 = acc[mt][nt][rh * 2 + 0] + b2[e * DIM + col];
                float f1 = acc[mt][nt][rh * 2 + 1] + b2[e * DIM + col + 1];
                atomicAdd(ob + col,     gw * f0);
                atomicAdd(ob + col + 1, gw * f1);
            }
        }
    }
}

// ======================= aux =======================
__global__ void aux_kernel(float* __restrict__ out, int out_size) {
    if (threadIdx.x == 0 && out_size >= N_TOK * DIM + 2) {
        float ent = g_ent / (float)N_TOK;
        float lb = 0.f;
#pragma unroll
        for (int e = 0; e < NE; e++) {
            float d = g_imp[e] / (float)N_TOK - 1.f / (float)NE;
            lb += d * d;
        }
        lb /= (float)NE;
        out[N_TOK * DIM]     = ent;
        out[N_TOK * DIM + 1] = lb;
    }
}

// ======================= launch =======================
extern "C" void kernel_launch(void* const* d_in, const int* in_sizes, int n_in,
                              void* d_out, int out_size) {
    const float* x  = (const float*)d_in[0];
    const float* rw = (const float*)d_in[1];
    const float* rb = (const float*)d_in[2];
    const float* w1 = (const float*)d_in[3];
    const float* b1 = (const float*)d_in[4];
    const float* w2 = (const float*)d_in[5];
    const float* b2 = (const float*)d_in[6];
    float* out = (float*)d_out;

    cudaFuncSetAttribute(gemm1_mma, cudaFuncAttributeMaxDynamicSharedMemorySize, SMEM_TOTAL);
    cudaFuncSetAttribute(gemm2_mma, cudaFuncAttributeMaxDynamicSharedMemorySize, SMEM_TOTAL);

    cudaMemsetAsync(d_out, 0, (size_t)out_size * sizeof(float), 0);
    zero_kernel<<<1, 32>>>();
    router_kernel<<<N_TOK / 8, 256>>>(x, rw, rb);
    offsets_kernel<<<1, 1>>>();

    convert_x_kernel<<<(N_TOK * DIM) / 1024, 256>>>(x);
    {
        dim3 g(HID / 32, DIM / 32, NE), b(32, 8);
        transpose_convert_kernel<<<g, b>>>(w1, 0, DIM, HID);
    }
    {
        dim3 g(DIM / 32, HID / 32, NE), b(32, 8);
        transpose_convert_kernel<<<g, b>>>(w2, 1, HID, DIM);
    }

    {
        dim3 g(HID / 256, N_TOK / 128, NE);
        gemm1_mma<<<g, 256, SMEM_TOTAL>>>(b1);
    }
    {
        dim3 g(DIM / 256, N_TOK / 128, NE);
        gemm2_mma<<<g, 256, SMEM_TOTAL>>>(b2, out);
    }
    aux_kernel<<<1, 1>>>(out, out_size);
}

// round 9
// speedup vs baseline: 2.0074x; 1.4468x over previous
#include <cuda_runtime.h>
#include <cuda_fp16.h>
#include <math.h>
#include <stdint.h>

#define N_TOK 8192
#define DIM   1024
#define HID   4096
#define NE    8
#define STRD  12

// ======================= PTX helpers =======================
__device__ __forceinline__ uint32_t smem_u32(const void* p) {
    uint32_t a;
    asm("{ .reg .u64 t; cvta.to.shared.u64 t, %1; cvt.u32.u64 %0, t; }" : "=r"(a) : "l"(p));
    return a;
}
#define CPA16(s, g) asm volatile("cp.async.cg.shared.global [%0], [%1], 16;" :: "r"(s), "l"(g))
#define CPC()       asm volatile("cp.async.commit_group;" ::: "memory")
#define CPW(n)      asm volatile("cp.async.wait_group %0;" :: "n"(n) : "memory")

__device__ __forceinline__ void mma_f16(float* d, const uint32_t* a, const uint32_t* b) {
    asm volatile("mma.sync.aligned.m16n8k16.row.col.f32.f16.f16.f32 "
                 "{%0,%1,%2,%3},{%4,%5,%6,%7},{%8,%9},{%0,%1,%2,%3};"
                 : "+f"(d[0]), "+f"(d[1]), "+f"(d[2]), "+f"(d[3])
                 : "r"(a[0]), "r"(a[1]), "r"(a[2]), "r"(a[3]), "r"(b[0]), "r"(b[1]));
}

// ======================= device scratch =======================
__device__ int   g_count[NE];
__device__ int   g_off[NE];
__device__ int   g_tok[NE * N_TOK];
__device__ float g_gate[NE * N_TOK];
__device__ float g_ent;
__device__ float g_imp[NE];

__device__ __align__(16) __half g_xh[(size_t)N_TOK * DIM];
__device__ __align__(16) __half g_w1h[(size_t)NE * HID * DIM];   // [e][n(hid)][k(dim)]
__device__ __align__(16) __half g_w2h[(size_t)NE * DIM * HID];   // [e][n(dim)][k(hid)]
__device__ __align__(16) __half g_hh[(size_t)2 * N_TOK * HID];   // [slot][hid]

// ======================= small kernels =======================
__global__ void zero_kernel() {
    int t = threadIdx.x;
    if (t < NE) { g_count[t] = 0; g_imp[t] = 0.f; }
    if (t == 0) g_ent = 0.f;
}

__global__ void router_kernel(const float* __restrict__ x,
                              const float* __restrict__ rw,
                              const float* __restrict__ rb) {
    __shared__ float s_ent[8];
    __shared__ float s_imp[8][NE];
    int warp = threadIdx.x >> 5;
    int lane = threadIdx.x & 31;
    int t = blockIdx.x * 8 + warp;

    float acc[NE];
#pragma unroll
    for (int e = 0; e < NE; e++) acc[e] = 0.f;
    const float* xr = x + (size_t)t * DIM;
    for (int k = lane; k < DIM; k += 32) {
        float xv = xr[k];
        const float* rwk = rw + k * NE;
#pragma unroll
        for (int e = 0; e < NE; e++) acc[e] += xv * rwk[e];
    }
#pragma unroll
    for (int e = 0; e < NE; e++)
#pragma unroll
        for (int s = 16; s > 0; s >>= 1)
            acc[e] += __shfl_xor_sync(0xffffffff, acc[e], s);

    if (lane == 0) {
        float lg[NE], m = -1e30f;
#pragma unroll
        for (int e = 0; e < NE; e++) { lg[e] = acc[e] + rb[e]; m = fmaxf(m, lg[e]); }
        float p[NE], sum = 0.f;
#pragma unroll
        for (int e = 0; e < NE; e++) { p[e] = expf(lg[e] - m); sum += p[e]; }
        float inv = 1.f / sum, ent = 0.f;
#pragma unroll
        for (int e = 0; e < NE; e++) {
            float pe = p[e] * inv;
            ent -= pe * logf(fmaxf(pe, 1e-8f));
            s_imp[warp][e] = pe;
        }
        s_ent[warp] = ent;
        int e0 = 0;
#pragma unroll
        for (int e = 1; e < NE; e++) if (lg[e] > lg[e0]) e0 = e;
        int e1 = (e0 == 0) ? 1 : 0;
#pragma unroll
        for (int e = 0; e < NE; e++) if (e != e0 && lg[e] > lg[e1]) e1 = e;
        float g0 = 1.f / (1.f + expf(lg[e1] - lg[e0]));
        float g1 = 1.f - g0;
        int p0 = atomicAdd(&g_count[e0], 1);
        g_tok [e0 * N_TOK + p0] = t; g_gate[e0 * N_TOK + p0] = g0;
        int p1 = atomicAdd(&g_count[e1], 1);
        g_tok [e1 * N_TOK + p1] = t; g_gate[e1 * N_TOK + p1] = g1;
    }
    __syncthreads();
    if (threadIdx.x < NE) {
        float se = 0.f;
#pragma unroll
        for (int w = 0; w < 8; w++) se += s_imp[w][threadIdx.x];
        atomicAdd(&g_imp[threadIdx.x], se);
    }
    if (threadIdx.x == 0) {
        float se = 0.f;
#pragma unroll
        for (int w = 0; w < 8; w++) se += s_ent[w];
        atomicAdd(&g_ent, se);
    }
}

__global__ void offsets_kernel() {
    if (threadIdx.x == 0) {
        int s = 0;
#pragma unroll
        for (int e = 0; e < NE; e++) { g_off[e] = s; s += g_count[e]; }
    }
}

__global__ void convert_x_kernel(const float* __restrict__ x) {
    size_t i = ((size_t)blockIdx.x * 256 + threadIdx.x) * 4;
    float4 v = *(const float4*)(x + i);
    uint32_t p0 = (uint32_t)__half_as_ushort(__float2half_rn(v.x))
                | ((uint32_t)__half_as_ushort(__float2half_rn(v.y)) << 16);
    uint32_t p1 = (uint32_t)__half_as_ushort(__float2half_rn(v.z))
                | ((uint32_t)__half_as_ushort(__float2half_rn(v.w)) << 16);
    *(uint2*)(g_xh + i) = make_uint2(p0, p1);
}

// transpose: src [e][R][C] fp32 -> INTERNAL dst [e][C][R] fp16
// which=0 -> g_w1h ; which=1 -> g_w2h   (never pass device globals as host args)
__global__ void transpose_convert_kernel(const float* __restrict__ src,
                                         int which, int R, int C) {
    __shared__ float t[32][33];
    __half* dh = which ? g_w2h : g_w1h;
    int e = blockIdx.z;
    int c0 = blockIdx.x * 32, r0 = blockIdx.y * 32;
    const float* s = src + (size_t)e * R * C;
#pragma unroll
    for (int i = threadIdx.y; i < 32; i += 8)
        t[i][threadIdx.x] = s[(size_t)(r0 + i) * C + c0 + threadIdx.x];
    __syncthreads();
#pragma unroll
    for (int i = threadIdx.y; i < 32; i += 8) {
        float v = t[threadIdx.x][i];
        size_t o = (size_t)e * R * C + (size_t)(c0 + i) * R + r0 + threadIdx.x;
        dh[o] = __float2half_rn(v);
    }
}

// ======================= cp.async stage loader =======================
// A tile 128 rows, B tile 256 rows, K-chunk 16 (32B), single fp16 term.
__device__ __forceinline__ void load_stage(
    uint32_t abase, uint32_t bbase,
    const __half* __restrict__ Ah, const __half* __restrict__ Bh,
    const uint32_t* __restrict__ arow, const uint32_t* __restrict__ brow,
    int k0, int buf)
{
    int tid = threadIdx.x;
    int row = tid >> 1, half = tid & 1;
    uint32_t hb = (uint32_t)half * 16u;

    uint32_t ka = arow[row] + k0 + half * 8;
    uint32_t da = abase + (uint32_t)buf * (128 * 48) + (uint32_t)row * 48 + hb;
    CPA16(da, Ah + ka);

    uint32_t kb0 = brow[row]       + k0 + half * 8;
    uint32_t kb1 = brow[row + 128] + k0 + half * 8;
    uint32_t db = bbase + (uint32_t)buf * (256 * 48) + (uint32_t)row * 48 + hb;
    CPA16(db,            Bh + kb0);
    CPA16(db + 128 * 48, Bh + kb1);
    CPC();
}

// ======================= GEMM mainloop: CTA 128x256, warp 64x64, 1-term fp16 =======================
__device__ __forceinline__ void mma_mainloop(
    uint32_t (*A)[128][STRD], uint32_t (*B)[256][STRD],
    const __half* __restrict__ Ah, const __half* __restrict__ Bh,
    const uint32_t* __restrict__ arow, const uint32_t* __restrict__ brow,
    int S, float (&acc)[4][8][4])
{
    int tid  = threadIdx.x;
    int lane = tid & 31;
    int wid  = tid >> 5;
    int wm   = wid & 1;        // 2 m-groups of 64
    int wn   = wid >> 1;       // 4 n-groups of 64
    int q    = lane & 3;
    int r4   = lane >> 2;

    uint32_t abase = smem_u32(&A[0][0][0]);
    uint32_t bbase = smem_u32(&B[0][0][0]);

    load_stage(abase, bbase, Ah, Bh, arow, brow, 0, 0);

    for (int s = 0; s < S; s++) {
        if (s + 1 < S) {
            load_stage(abase, bbase, Ah, Bh, arow, brow, (s + 1) * 16, (s + 1) & 1);
            CPW(1);
        } else {
            CPW(0);
        }
        __syncthreads();

        int bu = s & 1;
        uint32_t bhf[8][2];
#pragma unroll
        for (int nt = 0; nt < 8; nt++) {
            int nb = wn * 64 + nt * 8 + r4;
            bhf[nt][0] = B[bu][nb][q];
            bhf[nt][1] = B[bu][nb][4 + q];
        }
#pragma unroll
        for (int mt = 0; mt < 4; mt++) {
            int ra = wm * 64 + mt * 16 + r4;
            uint32_t ah[4];
            ah[0] = A[bu][ra][q];      ah[1] = A[bu][ra + 8][q];
            ah[2] = A[bu][ra][4 + q];  ah[3] = A[bu][ra + 8][4 + q];
#pragma unroll
            for (int nt = 0; nt < 8; nt++)
                mma_f16(acc[mt][nt], ah, bhf[nt]);
        }
        __syncthreads();   // reads of buf done before next iter overwrites it
    }
}

// ======================= GEMM1: h = relu(x @ w1 + b1) =======================
__global__ void __launch_bounds__(256)
gemm1_mma(const float* __restrict__ b1) {
    int e = blockIdx.z;
    int ce = g_count[e];
    int m0 = blockIdx.y * 128;
    if (m0 >= ce) return;
    int n0 = blockIdx.x * 256;
    int off = g_off[e];

    __shared__ __align__(16) uint32_t sA[2][128][STRD];
    __shared__ __align__(16) uint32_t sB[2][256][STRD];
    __shared__ uint32_t s_arow[128];
    __shared__ uint32_t s_brow[256];

    int tid = threadIdx.x;
    if (tid < 128) {
        int tok = (m0 + tid < ce) ? g_tok[e * N_TOK + m0 + tid] : 0;
        s_arow[tid] = (uint32_t)tok * DIM;
    }
    s_brow[tid] = (uint32_t)(e * HID + n0 + tid) * DIM;
    __syncthreads();

    float acc[4][8][4];
#pragma unroll
    for (int i = 0; i < 4; i++)
#pragma unroll
        for (int j = 0; j < 8; j++)
#pragma unroll
            for (int k = 0; k < 4; k++) acc[i][j][k] = 0.f;

    mma_mainloop(sA, sB, g_xh, g_w1h, s_arow, s_brow, DIM / 16, acc);

    int lane = tid & 31, wid = tid >> 5;
    int wm = wid & 1, wn = wid >> 1;
    int r = lane >> 2, q = lane & 3;
#pragma unroll
    for (int mt = 0; mt < 4; mt++) {
#pragma unroll
        for (int rh = 0; rh < 2; rh++) {
            int row = wm * 64 + mt * 16 + r + rh * 8;
            if (m0 + row >= ce) continue;
            size_t slot = (size_t)(off + m0 + row);
#pragma unroll
            for (int nt = 0; nt < 8; nt++) {
                int col = n0 + wn * 64 + nt * 8 + 2 * q;
                float f0 = acc[mt][nt][rh * 2 + 0] + b1[e * HID + col];
                float f1 = acc[mt][nt][rh * 2 + 1] + b1[e * HID + col + 1];
                f0 = fmaxf(f0, 0.f); f1 = fmaxf(f1, 0.f);
                uint32_t ph = (uint32_t)__half_as_ushort(__float2half_rn(f0))
                            | ((uint32_t)__half_as_ushort(__float2half_rn(f1)) << 16);
                *(uint32_t*)(g_hh + slot * HID + col) = ph;
            }
        }
    }
}

// ======================= GEMM2: out += gate * (h @ w2 + b2) =======================
__global__ void __launch_bounds__(256)
gemm2_mma(const float* __restrict__ b2, float* __restrict__ out) {
    int e = blockIdx.z;
    int ce = g_count[e];
    int m0 = blockIdx.y * 128;
    if (m0 >= ce) return;
    int n0 = blockIdx.x * 256;
    int off = g_off[e];

    __shared__ __align__(16) uint32_t sA[2][128][STRD];
    __shared__ __align__(16) uint32_t sB[2][256][STRD];
    __shared__ uint32_t s_arow[128];
    __shared__ uint32_t s_brow[256];

    int tid = threadIdx.x;
    if (tid < 128) {
        int sl = off + m0 + tid;
        if (sl > 2 * N_TOK - 1) sl = 2 * N_TOK - 1;
        s_arow[tid] = (uint32_t)sl * HID;
    }
    s_brow[tid] = (uint32_t)(e * DIM + n0 + tid) * HID;
    __syncthreads();

    float acc[4][8][4];
#pragma unroll
    for (int i = 0; i < 4; i++)
#pragma unroll
        for (int j = 0; j < 8; j++)
#pragma unroll
            for (int k = 0; k < 4; k++) acc[i][j][k] = 0.f;

    mma_mainloop(sA, sB, g_hh, g_w2h, s_arow, s_brow, HID / 16, acc);

    int lane = tid & 31, wid = tid >> 5;
    int wm = wid & 1, wn = wid >> 1;
    int r = lane >> 2, q = lane & 3;
#pragma unroll
    for (int mt = 0; mt < 4; mt++) {
#pragma unroll
        for (int rh = 0; rh < 2; rh++) {
            int row = wm * 64 + mt * 16 + r + rh * 8;
            if (m0 + row >= ce) continue;
            int slot2 = e * N_TOK + m0 + row;
            int tok = g_tok[slot2];
            float gw = g_gate[slot2];
            float* ob = out + (size_t)tok * DIM;
#pragma unroll
            for (int nt = 0; nt < 8; nt++) {
                int col = n0 + wn * 64 + nt * 8 + 2 * q;
                float f0 = acc[mt][nt][rh * 2 + 0] + b2[e * DIM + col];
                float f1 = acc[mt][nt][rh * 2 + 1] + b2[e * DIM + col + 1];
                atomicAdd(ob + col,     gw * f0);
                atomicAdd(ob + col + 1, gw * f1);
            }
        }
    }
}

// ======================= aux =======================
__global__ void aux_kernel(float* __restrict__ out, int out_size) {
    if (threadIdx.x == 0 && out_size >= N_TOK * DIM + 2) {
        float ent = g_ent / (float)N_TOK;
        float lb = 0.f;
#pragma unroll
        for (int e = 0; e < NE; e++) {
            float d = g_imp[e] / (float)N_TOK - 1.f / (float)NE;
            lb += d * d;
        }
        lb /= (float)NE;
        out[N_TOK * DIM]     = ent;
        out[N_TOK * DIM + 1] = lb;
    }
}

// ======================= launch =======================
extern "C" void kernel_launch(void* const* d_in, const int* in_sizes, int n_in,
                              void* d_out, int out_size) {
    const float* x  = (const float*)d_in[0];
    const float* rw = (const float*)d_in[1];
    const float* rb = (const float*)d_in[2];
    const float* w1 = (const float*)d_in[3];
    const float* b1 = (const float*)d_in[4];
    const float* w2 = (const float*)d_in[5];
    const float* b2 = (const float*)d_in[6];
    float* out = (float*)d_out;

    cudaMemsetAsync(d_out, 0, (size_t)out_size * sizeof(float), 0);
    zero_kernel<<<1, 32>>>();
    router_kernel<<<N_TOK / 8, 256>>>(x, rw, rb);
    offsets_kernel<<<1, 1>>>();

    convert_x_kernel<<<(N_TOK * DIM) / 1024, 256>>>(x);
    {
        dim3 g(HID / 32, DIM / 32, NE), b(32, 8);
        transpose_convert_kernel<<<g, b>>>(w1, 0, DIM, HID);
    }
    {
        dim3 g(DIM / 32, HID / 32, NE), b(32, 8);
        transpose_convert_kernel<<<g, b>>>(w2, 1, HID, DIM);
    }

    {
        dim3 g(HID / 256, N_TOK / 128, NE);
        gemm1_mma<<<g, 256>>>(b1);
    }
    {
        dim3 g(DIM / 256, N_TOK / 128, NE);
        gemm2_mma<<<g, 256>>>(b2, out);
    }
    aux_kernel<<<1, 1>>>(out, out_size);
}

// round 10
// speedup vs baseline: 2.0746x; 1.0335x over previous
#include <cuda_runtime.h>
#include <cuda_fp16.h>
#include <math.h>
#include <stdint.h>

#define N_TOK 8192
#define DIM   1024
#define HID   4096
#define NE    8
#define STRD  12

// dynamic smem layout (bytes)
#define OFF_A    0          // [4][128][STRD] u32 = 24576 (reused as h-staging post-loop)
#define OFF_B    24576      // [4][256][STRD] u32 = 49152
#define OFF_AROW 73728      // 128 u32
#define OFF_BROW 74240      // 256 u32
#define SMEM_TOTAL 75264

// ======================= PTX helpers =======================
__device__ __forceinline__ uint32_t smem_u32(const void* p) {
    uint32_t a;
    asm("{ .reg .u64 t; cvta.to.shared.u64 t, %1; cvt.u32.u64 %0, t; }" : "=r"(a) : "l"(p));
    return a;
}
#define CPA16(s, g) asm volatile("cp.async.cg.shared.global [%0], [%1], 16;" :: "r"(s), "l"(g))
#define CPC()       asm volatile("cp.async.commit_group;" ::: "memory")
#define CPW(n)      asm volatile("cp.async.wait_group %0;" :: "n"(n) : "memory")

__device__ __forceinline__ void mma_f16(float* d, const uint32_t* a, const uint32_t* b) {
    asm volatile("mma.sync.aligned.m16n8k16.row.col.f32.f16.f16.f32 "
                 "{%0,%1,%2,%3},{%4,%5,%6,%7},{%8,%9},{%0,%1,%2,%3};"
                 : "+f"(d[0]), "+f"(d[1]), "+f"(d[2]), "+f"(d[3])
                 : "r"(a[0]), "r"(a[1]), "r"(a[2]), "r"(a[3]), "r"(b[0]), "r"(b[1]));
}

// ======================= device scratch =======================
__device__ int   g_count[NE];
__device__ int   g_off[NE];
__device__ int   g_tok[NE * N_TOK];
__device__ float g_gate[NE * N_TOK];
__device__ float g_ent;
__device__ float g_imp[NE];

__device__ __align__(16) __half g_xh[(size_t)N_TOK * DIM];
__device__ __align__(16) __half g_w1h[(size_t)NE * HID * DIM];   // [e][n(hid)][k(dim)]
__device__ __align__(16) __half g_w2h[(size_t)NE * DIM * HID];   // [e][n(dim)][k(hid)]
__device__ __align__(16) __half g_hh[(size_t)2 * N_TOK * HID];   // [slot][hid]

// ======================= small kernels =======================
__global__ void zero_kernel() {
    int t = threadIdx.x;
    if (t < NE) { g_count[t] = 0; g_imp[t] = 0.f; }
    if (t == 0) g_ent = 0.f;
}

__global__ void router_kernel(const float* __restrict__ x,
                              const float* __restrict__ rw,
                              const float* __restrict__ rb) {
    __shared__ float s_ent[8];
    __shared__ float s_imp[8][NE];
    int warp = threadIdx.x >> 5;
    int lane = threadIdx.x & 31;
    int t = blockIdx.x * 8 + warp;

    float acc[NE];
#pragma unroll
    for (int e = 0; e < NE; e++) acc[e] = 0.f;
    const float* xr = x + (size_t)t * DIM;
    for (int k = lane; k < DIM; k += 32) {
        float xv = xr[k];
        const float* rwk = rw + k * NE;
#pragma unroll
        for (int e = 0; e < NE; e++) acc[e] += xv * rwk[e];
    }
#pragma unroll
    for (int e = 0; e < NE; e++)
#pragma unroll
        for (int s = 16; s > 0; s >>= 1)
            acc[e] += __shfl_xor_sync(0xffffffff, acc[e], s);

    if (lane == 0) {
        float lg[NE], m = -1e30f;
#pragma unroll
        for (int e = 0; e < NE; e++) { lg[e] = acc[e] + rb[e]; m = fmaxf(m, lg[e]); }
        float p[NE], sum = 0.f;
#pragma unroll
        for (int e = 0; e < NE; e++) { p[e] = expf(lg[e] - m); sum += p[e]; }
        float inv = 1.f / sum, ent = 0.f;
#pragma unroll
        for (int e = 0; e < NE; e++) {
            float pe = p[e] * inv;
            ent -= pe * logf(fmaxf(pe, 1e-8f));
            s_imp[warp][e] = pe;
        }
        s_ent[warp] = ent;
        int e0 = 0;
#pragma unroll
        for (int e = 1; e < NE; e++) if (lg[e] > lg[e0]) e0 = e;
        int e1 = (e0 == 0) ? 1 : 0;
#pragma unroll
        for (int e = 0; e < NE; e++) if (e != e0 && lg[e] > lg[e1]) e1 = e;
        float g0 = 1.f / (1.f + expf(lg[e1] - lg[e0]));
        float g1 = 1.f - g0;
        int p0 = atomicAdd(&g_count[e0], 1);
        g_tok [e0 * N_TOK + p0] = t; g_gate[e0 * N_TOK + p0] = g0;
        int p1 = atomicAdd(&g_count[e1], 1);
        g_tok [e1 * N_TOK + p1] = t; g_gate[e1 * N_TOK + p1] = g1;
    }
    __syncthreads();
    if (threadIdx.x < NE) {
        float se = 0.f;
#pragma unroll
        for (int w = 0; w < 8; w++) se += s_imp[w][threadIdx.x];
        atomicAdd(&g_imp[threadIdx.x], se);
    }
    if (threadIdx.x == 0) {
        float se = 0.f;
#pragma unroll
        for (int w = 0; w < 8; w++) se += s_ent[w];
        atomicAdd(&g_ent, se);
    }
}

__global__ void offsets_kernel() {
    if (threadIdx.x == 0) {
        int s = 0;
#pragma unroll
        for (int e = 0; e < NE; e++) { g_off[e] = s; s += g_count[e]; }
    }
}

__global__ void convert_x_kernel(const float* __restrict__ x) {
    size_t i = ((size_t)blockIdx.x * 256 + threadIdx.x) * 4;
    float4 v = *(const float4*)(x + i);
    uint32_t p0 = (uint32_t)__half_as_ushort(__float2half_rn(v.x))
                | ((uint32_t)__half_as_ushort(__float2half_rn(v.y)) << 16);
    uint32_t p1 = (uint32_t)__half_as_ushort(__float2half_rn(v.z))
                | ((uint32_t)__half_as_ushort(__float2half_rn(v.w)) << 16);
    *(uint2*)(g_xh + i) = make_uint2(p0, p1);
}

// transpose: src [e][R][C] fp32 -> INTERNAL dst [e][C][R] fp16
// which=0 -> g_w1h ; which=1 -> g_w2h   (never pass device globals as host args)
__global__ void transpose_convert_kernel(const float* __restrict__ src,
                                         int which, int R, int C) {
    __shared__ float t[32][33];
    __half* dh = which ? g_w2h : g_w1h;
    int e = blockIdx.z;
    int c0 = blockIdx.x * 32, r0 = blockIdx.y * 32;
    const float* s = src + (size_t)e * R * C;
#pragma unroll
    for (int i = threadIdx.y; i < 32; i += 8)
        t[i][threadIdx.x] = s[(size_t)(r0 + i) * C + c0 + threadIdx.x];
    __syncthreads();
#pragma unroll
    for (int i = threadIdx.y; i < 32; i += 8) {
        float v = t[threadIdx.x][i];
        size_t o = (size_t)e * R * C + (size_t)(c0 + i) * R + r0 + threadIdx.x;
        dh[o] = __float2half_rn(v);
    }
}

// ======================= cp.async stage loader =======================
// A tile 128 rows, B tile 256 rows, K-chunk 16 (32B). buf in 0..3.
__device__ __forceinline__ void load_stage(
    uint32_t abase, uint32_t bbase,
    const __half* __restrict__ Ah, const __half* __restrict__ Bh,
    const uint32_t* __restrict__ arow, const uint32_t* __restrict__ brow,
    int k0, int buf)
{
    int tid = threadIdx.x;
    int row = tid >> 1, half = tid & 1;
    uint32_t hb = (uint32_t)half * 16u;

    uint32_t ka = arow[row] + k0 + half * 8;
    uint32_t da = abase + (uint32_t)buf * (128 * 48) + (uint32_t)row * 48 + hb;
    CPA16(da, Ah + ka);

    uint32_t kb0 = brow[row]       + k0 + half * 8;
    uint32_t kb1 = brow[row + 128] + k0 + half * 8;
    uint32_t db = bbase + (uint32_t)buf * (256 * 48) + (uint32_t)row * 48 + hb;
    CPA16(db,            Bh + kb0);
    CPA16(db + 128 * 48, Bh + kb1);
    CPC();
}

// ======================= GEMM mainloop: CTA 128x256, warp 64x64 =======================
// 4-stage cp.async pipeline, ONE __syncthreads per stage.
// Order per iter s: wait_group 2 (stage s data resident) -> barrier (all warps done
// computing s-1 => buffer (s+3)&3 reusable) -> issue load s+3 -> compute s.
__device__ __forceinline__ void mma_mainloop(
    char* smc,
    const __half* __restrict__ Ah, const __half* __restrict__ Bh,
    const uint32_t* __restrict__ arow, const uint32_t* __restrict__ brow,
    int S, float (&acc)[4][8][4])
{
    int tid  = threadIdx.x;
    int lane = tid & 31;
    int wid  = tid >> 5;
    int wm   = wid & 1;        // 2 m-groups of 64
    int wn   = wid >> 1;       // 4 n-groups of 64
    int q    = lane & 3;
    int r4   = lane >> 2;

    uint32_t (*A)[128][STRD] = (uint32_t (*)[128][STRD])(smc + OFF_A);
    uint32_t (*B)[256][STRD] = (uint32_t (*)[256][STRD])(smc + OFF_B);
    uint32_t abase = smem_u32(&A[0][0][0]);
    uint32_t bbase = smem_u32(&B[0][0][0]);

    load_stage(abase, bbase, Ah, Bh, arow, brow, 0,  0);
    load_stage(abase, bbase, Ah, Bh, arow, brow, 16, 1);
    load_stage(abase, bbase, Ah, Bh, arow, brow, 32, 2);

    for (int s = 0; s < S; s++) {
        CPW(2);
        __syncthreads();
        if (s + 3 < S)
            load_stage(abase, bbase, Ah, Bh, arow, brow, (s + 3) * 16, (s + 3) & 3);
        else
            CPC();   // keep group count uniform

        int bu = s & 3;
        uint32_t bhf[8][2];
#pragma unroll
        for (int nt = 0; nt < 8; nt++) {
            int nb = wn * 64 + nt * 8 + r4;
            bhf[nt][0] = B[bu][nb][q];
            bhf[nt][1] = B[bu][nb][4 + q];
        }
#pragma unroll
        for (int mt = 0; mt < 4; mt++) {
            int ra = wm * 64 + mt * 16 + r4;
            uint32_t ah[4];
            ah[0] = A[bu][ra][q];      ah[1] = A[bu][ra + 8][q];
            ah[2] = A[bu][ra][4 + q];  ah[3] = A[bu][ra + 8][4 + q];
#pragma unroll
            for (int nt = 0; nt < 8; nt++)
                mma_f16(acc[mt][nt], ah, bhf[nt]);
        }
    }
    __syncthreads();   // all compute done before smem reuse by epilogue
}

// ======================= GEMM1: h = relu(x @ w1 + b1) =======================
__global__ void __launch_bounds__(256)
gemm1_mma(const float* __restrict__ b1) {
    int e = blockIdx.z;
    int ce = g_count[e];
    int m0 = blockIdx.y * 128;
    if (m0 >= ce) return;
    int n0 = blockIdx.x * 256;
    int off = g_off[e];

    extern __shared__ char smc[];
    uint32_t* s_arow = (uint32_t*)(smc + OFF_AROW);
    uint32_t* s_brow = (uint32_t*)(smc + OFF_BROW);

    int tid = threadIdx.x;
    if (tid < 128) {
        int tok = (m0 + tid < ce) ? g_tok[e * N_TOK + m0 + tid] : 0;
        s_arow[tid] = (uint32_t)tok * DIM;
    }
    s_brow[tid] = (uint32_t)(e * HID + n0 + tid) * DIM;
    __syncthreads();

    float acc[4][8][4];
#pragma unroll
    for (int i = 0; i < 4; i++)
#pragma unroll
        for (int j = 0; j < 8; j++)
#pragma unroll
            for (int k = 0; k < 4; k++) acc[i][j][k] = 0.f;

    mma_mainloop(smc, g_xh, g_w1h, s_arow, s_brow, DIM / 16, acc);

    // epilogue: bias + relu -> stage 16x64 fp16 tile in smem -> coalesced 16B stores
    int lane = tid & 31, wid = tid >> 5;
    int wm = wid & 1, wn = wid >> 1;
    int r = lane >> 2, q = lane & 3;
    __half* stg = (__half*)(smc + OFF_A) + (size_t)wid * 1152;  // 16 rows x 72 (2304B/warp)
    const float* brow_b1 = b1 + e * HID + n0 + wn * 64;
    int lr2 = lane >> 1, half2 = lane & 1;

#pragma unroll
    for (int mt = 0; mt < 4; mt++) {
#pragma unroll
        for (int rh = 0; rh < 2; rh++) {
            int lr = r + rh * 8;
#pragma unroll
            for (int nt = 0; nt < 8; nt++) {
                int lc = nt * 8 + 2 * q;
                float f0 = fmaxf(acc[mt][nt][rh * 2 + 0] + brow_b1[lc],     0.f);
                float f1 = fmaxf(acc[mt][nt][rh * 2 + 1] + brow_b1[lc + 1], 0.f);
                uint32_t ph = (uint32_t)__half_as_ushort(__float2half_rn(f0))
                            | ((uint32_t)__half_as_ushort(__float2half_rn(f1)) << 16);
                *(uint32_t*)(stg + lr * 72 + lc) = ph;
            }
        }
        __syncwarp();
        int grow = wm * 64 + mt * 16 + lr2;
        if (m0 + grow < ce) {
            size_t slot = (size_t)(off + m0 + grow);
            __half* dst = g_hh + slot * HID + n0 + wn * 64 + half2 * 32;
            const __half* srcp = stg + lr2 * 72 + half2 * 32;
#pragma unroll
            for (int c = 0; c < 4; c++)
                *(uint4*)(dst + c * 8) = *(const uint4*)(srcp + c * 8);
        }
        __syncwarp();
    }
}

// ======================= GEMM2: out += gate * (h @ w2 + b2) =======================
__global__ void __launch_bounds__(256)
gemm2_mma(const float* __restrict__ b2, float* __restrict__ out) {
    int e = blockIdx.z;
    int ce = g_count[e];
    int m0 = blockIdx.y * 128;
    if (m0 >= ce) return;
    int n0 = blockIdx.x * 256;
    int off = g_off[e];

    extern __shared__ char smc[];
    uint32_t* s_arow = (uint32_t*)(smc + OFF_AROW);
    uint32_t* s_brow = (uint32_t*)(smc + OFF_BROW);

    int tid = threadIdx.x;
    if (tid < 128) {
        int sl = off + m0 + tid;
        if (sl > 2 * N_TOK - 1) sl = 2 * N_TOK - 1;
        s_arow[tid] = (uint32_t)sl * HID;
    }
    s_brow[tid] = (uint32_t)(e * DIM + n0 + tid) * HID;
    __syncthreads();

    float acc[4][8][4];
#pragma unroll
    for (int i = 0; i < 4; i++)
#pragma unroll
        for (int j = 0; j < 8; j++)
#pragma unroll
            for (int k = 0; k < 4; k++) acc[i][j][k] = 0.f;

    mma_mainloop(smc, g_hh, g_w2h, s_arow, s_brow, HID / 16, acc);

    // epilogue: gate-weighted atomic add
    int lane = tid & 31, wid = tid >> 5;
    int wm = wid & 1, wn = wid >> 1;
    int r = lane >> 2, q = lane & 3;
#pragma unroll
    for (int mt = 0; mt < 4; mt++) {
#pragma unroll
        for (int rh = 0; rh < 2; rh++) {
            int row = wm * 64 + mt * 16 + r + rh * 8;
            if (m0 + row >= ce) continue;
            int slot2 = e * N_TOK + m0 + row;
            int tok = g_tok[slot2];
            float gw = g_gate[slot2];
            float* ob = out + (size_t)tok * DIM;
#pragma unroll
            for (int nt = 0; nt < 8; nt++) {
                int col = n0 + wn * 64 + nt * 8 + 2 * q;
                float f0 = acc[mt][nt][rh * 2 + 0] + b2[e * DIM + col];
                float f1 = acc[mt][nt][rh * 2 + 1] + b2[e * DIM + col + 1];
                atomicAdd(ob + col,     gw * f0);
                atomicAdd(ob + col + 1, gw * f1);
            }
        }
    }
}

// ======================= aux =======================
__global__ void aux_kernel(float* __restrict__ out, int out_size) {
    if (threadIdx.x == 0 && out_size >= N_TOK * DIM + 2) {
        float ent = g_ent / (float)N_TOK;
        float lb = 0.f;
#pragma unroll
        for (int e = 0; e < NE; e++) {
            float d = g_imp[e] / (float)N_TOK - 1.f / (float)NE;
            lb += d * d;
        }
        lb /= (float)NE;
        out[N_TOK * DIM]     = ent;
        out[N_TOK * DIM + 1] = lb;
    }
}

// ======================= launch =======================
extern "C" void kernel_launch(void* const* d_in, const int* in_sizes, int n_in,
                              void* d_out, int out_size) {
    const float* x  = (const float*)d_in[0];
    const float* rw = (const float*)d_in[1];
    const float* rb = (const float*)d_in[2];
    const float* w1 = (const float*)d_in[3];
    const float* b1 = (const float*)d_in[4];
    const float* w2 = (const float*)d_in[5];
    const float* b2 = (const float*)d_in[6];
    float* out = (float*)d_out;

    cudaFuncSetAttribute(gemm1_mma, cudaFuncAttributeMaxDynamicSharedMemorySize, SMEM_TOTAL);
    cudaFuncSetAttribute(gemm2_mma, cudaFuncAttributeMaxDynamicSharedMemorySize, SMEM_TOTAL);

    cudaMemsetAsync(d_out, 0, (size_t)out_size * sizeof(float), 0);
    zero_kernel<<<1, 32>>>();
    router_kernel<<<N_TOK / 8, 256>>>(x, rw, rb);
    offsets_kernel<<<1, 1>>>();

    convert_x_kernel<<<(N_TOK * DIM) / 1024, 256>>>(x);
    {
        dim3 g(HID / 32, DIM / 32, NE), b(32, 8);
        transpose_convert_kernel<<<g, b>>>(w1, 0, DIM, HID);
    }
    {
        dim3 g(DIM / 32, HID / 32, NE), b(32, 8);
        transpose_convert_kernel<<<g, b>>>(w2, 1, HID, DIM);
    }

    {
        dim3 g(HID / 256, N_TOK / 128, NE);
        gemm1_mma<<<g, 256, SMEM_TOTAL>>>(b1);
    }
    {
        dim3 g(DIM / 256, N_TOK / 128, NE);
        gemm2_mma<<<g, 256, SMEM_TOTAL>>>(b2, out);
    }
    aux_kernel<<<1, 1>>>(out, out_size);
}

// round 12
// speedup vs baseline: 2.3532x; 1.1343x over previous
#include <cuda_runtime.h>
#include <cuda_fp16.h>
#include <math.h>
#include <stdint.h>

#define N_TOK 8192
#define DIM   1024
#define HID   4096
#define NE    8

// dynamic smem layout (bytes). Rows are 80B (64B data + 16B pad):
// cp.async-aligned (80 = 5*16) and gather words 20r+q mod 32 are a permutation.
#define OFF_A    0          // [3][128][20] u32 = 30720 (reused as h-staging post-loop)
#define OFF_B    30720      // [3][256][20] u32 = 61440
#define OFF_AROW 92160      // 128 u32
#define OFF_BROW 92672      // 256 u32
#define SMEM_TOTAL 93696

// ======================= PTX helpers =======================
__device__ __forceinline__ uint32_t smem_u32(const void* p) {
    uint32_t a;
    asm("{ .reg .u64 t; cvta.to.shared.u64 t, %1; cvt.u32.u64 %0, t; }" : "=r"(a) : "l"(p));
    return a;
}
#define CPA16(s, g) asm volatile("cp.async.cg.shared.global [%0], [%1], 16;" :: "r"(s), "l"(g))
#define CPC()       asm volatile("cp.async.commit_group;" ::: "memory")
#define CPW(n)      asm volatile("cp.async.wait_group %0;" :: "n"(n) : "memory")

__device__ __forceinline__ void mma_f16(float* d, const uint32_t* a, const uint32_t* b) {
    asm volatile("mma.sync.aligned.m16n8k16.row.col.f32.f16.f16.f32 "
                 "{%0,%1,%2,%3},{%4,%5,%6,%7},{%8,%9},{%0,%1,%2,%3};"
                 : "+f"(d[0]), "+f"(d[1]), "+f"(d[2]), "+f"(d[3])
                 : "r"(a[0]), "r"(a[1]), "r"(a[2]), "r"(a[3]), "r"(b[0]), "r"(b[1]));
}

// ======================= device scratch =======================
__device__ int   g_count[NE];
__device__ int   g_off[NE];
__device__ int   g_tok[NE * N_TOK];
__device__ float g_gate[NE * N_TOK];
__device__ float g_ent;
__device__ float g_imp[NE];

__device__ __align__(16) __half g_xh[(size_t)N_TOK * DIM];
__device__ __align__(16) __half g_w1h[(size_t)NE * HID * DIM];   // [e][n(hid)][k(dim)]
__device__ __align__(16) __half g_w2h[(size_t)NE * DIM * HID];   // [e][n(dim)][k(hid)]
__device__ __align__(16) __half g_hh[(size_t)2 * N_TOK * HID];   // [slot][hid]

// ======================= small kernels =======================
__global__ void zero_kernel() {
    int t = threadIdx.x;
    if (t < NE) { g_count[t] = 0; g_imp[t] = 0.f; }
    if (t == 0) g_ent = 0.f;
}

__global__ void router_kernel(const float* __restrict__ x,
                              const float* __restrict__ rw,
                              const float* __restrict__ rb) {
    __shared__ float s_ent[8];
    __shared__ float s_imp[8][NE];
    int warp = threadIdx.x >> 5;
    int lane = threadIdx.x & 31;
    int t = blockIdx.x * 8 + warp;

    float acc[NE];
#pragma unroll
    for (int e = 0; e < NE; e++) acc[e] = 0.f;
    const float* xr = x + (size_t)t * DIM;
    for (int k = lane; k < DIM; k += 32) {
        float xv = xr[k];
        const float* rwk = rw + k * NE;
#pragma unroll
        for (int e = 0; e < NE; e++) acc[e] += xv * rwk[e];
    }
#pragma unroll
    for (int e = 0; e < NE; e++)
#pragma unroll
        for (int s = 16; s > 0; s >>= 1)
            acc[e] += __shfl_xor_sync(0xffffffff, acc[e], s);

    if (lane == 0) {
        float lg[NE], m = -1e30f;
#pragma unroll
        for (int e = 0; e < NE; e++) { lg[e] = acc[e] + rb[e]; m = fmaxf(m, lg[e]); }
        float p[NE], sum = 0.f;
#pragma unroll
        for (int e = 0; e < NE; e++) { p[e] = expf(lg[e] - m); sum += p[e]; }
        float inv = 1.f / sum, ent = 0.f;
#pragma unroll
        for (int e = 0; e < NE; e++) {
            float pe = p[e] * inv;
            ent -= pe * logf(fmaxf(pe, 1e-8f));
            s_imp[warp][e] = pe;
        }
        s_ent[warp] = ent;
        int e0 = 0;
#pragma unroll
        for (int e = 1; e < NE; e++) if (lg[e] > lg[e0]) e0 = e;
        int e1 = (e0 == 0) ? 1 : 0;
#pragma unroll
        for (int e = 0; e < NE; e++) if (e != e0 && lg[e] > lg[e1]) e1 = e;
        float g0 = 1.f / (1.f + expf(lg[e1] - lg[e0]));
        float g1 = 1.f - g0;
        int p0 = atomicAdd(&g_count[e0], 1);
        g_tok [e0 * N_TOK + p0] = t; g_gate[e0 * N_TOK + p0] = g0;
        int p1 = atomicAdd(&g_count[e1], 1);
        g_tok [e1 * N_TOK + p1] = t; g_gate[e1 * N_TOK + p1] = g1;
    }
    __syncthreads();
    if (threadIdx.x < NE) {
        float se = 0.f;
#pragma unroll
        for (int w = 0; w < 8; w++) se += s_imp[w][threadIdx.x];
        atomicAdd(&g_imp[threadIdx.x], se);
    }
    if (threadIdx.x == 0) {
        float se = 0.f;
#pragma unroll
        for (int w = 0; w < 8; w++) se += s_ent[w];
        atomicAdd(&g_ent, se);
    }
}

__global__ void offsets_kernel() {
    if (threadIdx.x == 0) {
        int s = 0;
#pragma unroll
        for (int e = 0; e < NE; e++) { g_off[e] = s; s += g_count[e]; }
    }
}

__global__ void convert_x_kernel(const float* __restrict__ x) {
    size_t i = ((size_t)blockIdx.x * 256 + threadIdx.x) * 4;
    float4 v = *(const float4*)(x + i);
    uint32_t p0 = (uint32_t)__half_as_ushort(__float2half_rn(v.x))
                | ((uint32_t)__half_as_ushort(__float2half_rn(v.y)) << 16);
    uint32_t p1 = (uint32_t)__half_as_ushort(__float2half_rn(v.z))
                | ((uint32_t)__half_as_ushort(__float2half_rn(v.w)) << 16);
    *(uint2*)(g_xh + i) = make_uint2(p0, p1);
}

// transpose: src [e][R][C] fp32 -> INTERNAL dst [e][C][R] fp16, 8B vector stores.
// which=0 -> g_w1h ; which=1 -> g_w2h   (never pass device globals as host args)
__global__ void transpose_convert_kernel(const float* __restrict__ src,
                                         int which, int R, int C) {
    __shared__ float t[32][33];
    __half* dh = which ? g_w2h : g_w1h;
    int e = blockIdx.z;
    int c0 = blockIdx.x * 32, r0 = blockIdx.y * 32;
    const float* s = src + (size_t)e * R * C;
    int tx = threadIdx.x & 31, ty = threadIdx.x >> 5;
#pragma unroll
    for (int i = ty; i < 32; i += 8)
        t[i][tx] = s[(size_t)(r0 + i) * C + c0 + tx];
    __syncthreads();
    // each thread: output column co (src col), 4 consecutive output rows rg..rg+3
    int co = threadIdx.x >> 3;
    int rg = (threadIdx.x & 7) * 4;
    __half h0 = __float2half_rn(t[rg + 0][co]);
    __half h1 = __float2half_rn(t[rg + 1][co]);
    __half h2 = __float2half_rn(t[rg + 2][co]);
    __half h3 = __float2half_rn(t[rg + 3][co]);
    uint2 v;
    v.x = (uint32_t)__half_as_ushort(h0) | ((uint32_t)__half_as_ushort(h1) << 16);
    v.y = (uint32_t)__half_as_ushort(h2) | ((uint32_t)__half_as_ushort(h3) << 16);
    size_t o = (size_t)e * R * C + (size_t)(c0 + co) * R + r0 + rg;
    *(uint2*)(dh + o) = v;
}

// ======================= cp.async stage loader (K-chunk 32 = 64B/row) =======================
__device__ __forceinline__ void load_stage(
    uint32_t abase, uint32_t bbase,
    const __half* __restrict__ Ah, const __half* __restrict__ Bh,
    const uint32_t* __restrict__ arow, const uint32_t* __restrict__ brow,
    int k0, int buf)
{
    int tid = threadIdx.x;
    int row = tid >> 1, hf = tid & 1;

    uint32_t ka = arow[row] + k0 + hf * 16;
    uint32_t da = abase + (uint32_t)buf * (128 * 80) + (uint32_t)row * 80 + hf * 32;
    CPA16(da,      Ah + ka);
    CPA16(da + 16, Ah + ka + 8);

    uint32_t kb0 = brow[row]       + k0 + hf * 16;
    uint32_t kb1 = brow[row + 128] + k0 + hf * 16;
    uint32_t db = bbase + (uint32_t)buf * (256 * 80) + (uint32_t)row * 80 + hf * 32;
    CPA16(db,                 Bh + kb0);
    CPA16(db + 16,            Bh + kb0 + 8);
    CPA16(db + 128 * 80,      Bh + kb1);
    CPA16(db + 128 * 80 + 16, Bh + kb1 + 8);
    CPC();
}

// ======================= GEMM mainloop: CTA 128x256, warp 64x64 =======================
// K-stage 32, 3-buffer cp.async pipeline, ONE __syncthreads per stage.
__device__ __forceinline__ void mma_mainloop(
    char* smc,
    const __half* __restrict__ Ah, const __half* __restrict__ Bh,
    const uint32_t* __restrict__ arow, const uint32_t* __restrict__ brow,
    int S, float (&acc)[4][8][4])
{
    int tid  = threadIdx.x;
    int lane = tid & 31;
    int wid  = tid >> 5;
    int wm   = wid & 1;        // 2 m-groups of 64
    int wn   = wid >> 1;       // 4 n-groups of 64
    int q    = lane & 3;
    int r4   = lane >> 2;

    uint32_t (*A)[128][20] = (uint32_t (*)[128][20])(smc + OFF_A);
    uint32_t (*B)[256][20] = (uint32_t (*)[256][20])(smc + OFF_B);
    uint32_t abase = smem_u32(&A[0][0][0]);
    uint32_t bbase = smem_u32(&B[0][0][0]);

    load_stage(abase, bbase, Ah, Bh, arow, brow, 0,  0);
    load_stage(abase, bbase, Ah, Bh, arow, brow, 32, 1);

    int bu = 0, bnx = 2;
    for (int s = 0; s < S; s++) {
        CPW(1);
        __syncthreads();
        if (s + 2 < S)
            load_stage(abase, bbase, Ah, Bh, arow, brow, (s + 2) * 32, bnx);
        else
            CPC();   // keep group accounting uniform

#pragma unroll
        for (int kc = 0; kc < 2; kc++) {
            int kq = kc * 8 + q;
            uint32_t bhf[8][2];
#pragma unroll
            for (int nt = 0; nt < 8; nt++) {
                int nb = wn * 64 + nt * 8 + r4;
                bhf[nt][0] = B[bu][nb][kq];
                bhf[nt][1] = B[bu][nb][kq + 4];
            }
#pragma unroll
            for (int mt = 0; mt < 4; mt++) {
                int ra = wm * 64 + mt * 16 + r4;
                uint32_t ah[4];
                ah[0] = A[bu][ra][kq];      ah[1] = A[bu][ra + 8][kq];
                ah[2] = A[bu][ra][kq + 4];  ah[3] = A[bu][ra + 8][kq + 4];
#pragma unroll
                for (int nt = 0; nt < 8; nt++)
                    mma_f16(acc[mt][nt], ah, bhf[nt]);
            }
        }
        bu = (bu == 2) ? 0 : bu + 1;
        bnx = (bnx == 2) ? 0 : bnx + 1;
    }
    __syncthreads();   // all compute done before smem reuse by epilogue
}

// ======================= GEMM1: h = relu(x @ w1 + b1) =======================
__global__ void __launch_bounds__(256)
gemm1_mma(const float* __restrict__ b1) {
    int e = blockIdx.z;
    int ce = g_count[e];
    int m0 = blockIdx.y * 128;
    if (m0 >= ce) return;
    int n0 = blockIdx.x * 256;
    int off = g_off[e];

    extern __shared__ char smc[];
    uint32_t* s_arow = (uint32_t*)(smc + OFF_AROW);
    uint32_t* s_brow = (uint32_t*)(smc + OFF_BROW);

    int tid = threadIdx.x;
    if (tid < 128) {
        int tok = (m0 + tid < ce) ? g_tok[e * N_TOK + m0 + tid] : 0;
        s_arow[tid] = (uint32_t)tok * DIM;
    }
    s_brow[tid] = (uint32_t)(e * HID + n0 + tid) * DIM;
    __syncthreads();

    float acc[4][8][4];
#pragma unroll
    for (int i = 0; i < 4; i++)
#pragma unroll
        for (int j = 0; j < 8; j++)
#pragma unroll
            for (int k = 0; k < 4; k++) acc[i][j][k] = 0.f;

    mma_mainloop(smc, g_xh, g_w1h, s_arow, s_brow, DIM / 32, acc);

    // epilogue: bias + relu -> stage 16x64 fp16 tile in smem -> coalesced 16B stores
    int lane = tid & 31, wid = tid >> 5;
    int wm = wid & 1, wn = wid >> 1;
    int r = lane >> 2, q = lane & 3;
    __half* stg = (__half*)(smc + OFF_A) + (size_t)wid * 1152;  // 16 rows x 72
    const float* brow_b1 = b1 + e * HID + n0 + wn * 64;
    int lr2 = lane >> 1, half2 = lane & 1;

#pragma unroll
    for (int mt = 0; mt < 4; mt++) {
#pragma unroll
        for (int rh = 0; rh < 2; rh++) {
            int lr = r + rh * 8;
#pragma unroll
            for (int nt = 0; nt < 8; nt++) {
                int lc = nt * 8 + 2 * q;
                float f0 = fmaxf(acc[mt][nt][rh * 2 + 0] + brow_b1[lc],     0.f);
                float f1 = fmaxf(acc[mt][nt][rh * 2 + 1] + brow_b1[lc + 1], 0.f);
                uint32_t ph = (uint32_t)__half_as_ushort(__float2half_rn(f0))
                            | ((uint32_t)__half_as_ushort(__float2half_rn(f1)) << 16);
                *(uint32_t*)(stg + lr * 72 + lc) = ph;
            }
        }
        __syncwarp();
        int grow = wm * 64 + mt * 16 + lr2;
        if (m0 + grow < ce) {
            size_t slot = (size_t)(off + m0 + grow);
            __half* dst = g_hh + slot * HID + n0 + wn * 64 + half2 * 32;
            const __half* srcp = stg + lr2 * 72 + half2 * 32;
#pragma unroll
            for (int c = 0; c < 4; c++)
                *(uint4*)(dst + c * 8) = *(const uint4*)(srcp + c * 8);
        }
        __syncwarp();
    }
}

// ======================= GEMM2: out += gate * (h @ w2 + b2) =======================
__global__ void __launch_bounds__(256)
gemm2_mma(const float* __restrict__ b2, float* __restrict__ out) {
    int e = blockIdx.z;
    int ce = g_count[e];
    int m0 = blockIdx.y * 128;
    if (m0 >= ce) return;
    int n0 = blockIdx.x * 256;
    int off = g_off[e];

    extern __shared__ char smc[];
    uint32_t* s_arow = (uint32_t*)(smc + OFF_AROW);
    uint32_t* s_brow = (uint32_t*)(smc + OFF_BROW);

    int tid = threadIdx.x;
    if (tid < 128) {
        int sl = off + m0 + tid;
        if (sl > 2 * N_TOK - 1) sl = 2 * N_TOK - 1;
        s_arow[tid] = (uint32_t)sl * HID;
    }
    s_brow[tid] = (uint32_t)(e * DIM + n0 + tid) * HID;
    __syncthreads();

    float acc[4][8][4];
#pragma unroll
    for (int i = 0; i < 4; i++)
#pragma unroll
        for (int j = 0; j < 8; j++)
#pragma unroll
            for (int k = 0; k < 4; k++) acc[i][j][k] = 0.f;

    mma_mainloop(smc, g_hh, g_w2h, s_arow, s_brow, HID / 32, acc);

    // epilogue: gate-weighted atomic add
    int lane = tid & 31, wid = tid >> 5;
    int wm = wid & 1, wn = wid >> 1;
    int r = lane >> 2, q = lane & 3;
#pragma unroll
    for (int mt = 0; mt < 4; mt++) {
#pragma unroll
        for (int rh = 0; rh < 2; rh++) {
            int row = wm * 64 + mt * 16 + r + rh * 8;
            if (m0 + row >= ce) continue;
            int slot2 = e * N_TOK + m0 + row;
            int tok = g_tok[slot2];
            float gw = g_gate[slot2];
            float* ob = out + (size_t)tok * DIM;
#pragma unroll
            for (int nt = 0; nt < 8; nt++) {
                int col = n0 + wn * 64 + nt * 8 + 2 * q;
                float f0 = acc[mt][nt][rh * 2 + 0] + b2[e * DIM + col];
                float f1 = acc[mt][nt][rh * 2 + 1] + b2[e * DIM + col + 1];
                atomicAdd(ob + col,     gw * f0);
                atomicAdd(ob + col + 1, gw * f1);
            }
        }
    }
}

// ======================= aux =======================
__global__ void aux_kernel(float* __restrict__ out, int out_size) {
    if (threadIdx.x == 0 && out_size >= N_TOK * DIM + 2) {
        float ent = g_ent / (float)N_TOK;
        float lb = 0.f;
#pragma unroll
        for (int e = 0; e < NE; e++) {
            float d = g_imp[e] / (float)N_TOK - 1.f / (float)NE;
            lb += d * d;
        }
        lb /= (float)NE;
        out[N_TOK * DIM]     = ent;
        out[N_TOK * DIM + 1] = lb;
    }
}

// ======================= launch (single stream — no stream/event objects) =======================
extern "C" void kernel_launch(void* const* d_in, const int* in_sizes, int n_in,
                              void* d_out, int out_size) {
    const float* x  = (const float*)d_in[0];
    const float* rw = (const float*)d_in[1];
    const float* rb = (const float*)d_in[2];
    const float* w1 = (const float*)d_in[3];
    const float* b1 = (const float*)d_in[4];
    const float* w2 = (const float*)d_in[5];
    const float* b2 = (const float*)d_in[6];
    float* out = (float*)d_out;

    cudaFuncSetAttribute(gemm1_mma, cudaFuncAttributeMaxDynamicSharedMemorySize, SMEM_TOTAL);
    cudaFuncSetAttribute(gemm2_mma, cudaFuncAttributeMaxDynamicSharedMemorySize, SMEM_TOTAL);

    cudaMemsetAsync(d_out, 0, (size_t)out_size * sizeof(float), 0);
    zero_kernel<<<1, 32>>>();
    router_kernel<<<N_TOK / 8, 256>>>(x, rw, rb);
    offsets_kernel<<<1, 1>>>();
    convert_x_kernel<<<(N_TOK * DIM) / 1024, 256>>>(x);
    {
        dim3 g(HID / 32, DIM / 32, NE);
        transpose_convert_kernel<<<g, 256>>>(w1, 0, DIM, HID);
    }
    {
        dim3 g(DIM / 32, HID / 32, NE);
        transpose_convert_kernel<<<g, 256>>>(w2, 1, HID, DIM);
    }

    {
        dim3 g(HID / 256, N_TOK / 128, NE);
        gemm1_mma<<<g, 256, SMEM_TOTAL>>>(b1);
    }
    {
        dim3 g(DIM / 256, N_TOK / 128, NE);
        gemm2_mma<<<g, 256, SMEM_TOTAL>>>(b2, out);
    }
    aux_kernel<<<1, 1>>>(out, out_size);
}

// round 13
// speedup vs baseline: 2.3650x; 1.0050x over previous
#include <cuda_runtime.h>
#include <cuda_fp16.h>
#include <math.h>
#include <stdint.h>

#define N_TOK 8192
#define DIM   1024
#define HID   4096
#define NE    8

// dynamic smem layout (bytes). Rows are 80B (64B data + 16B pad):
// cp.async-aligned (80 = 5*16) and gather words 20r+q mod 32 are a permutation.
#define OFF_A    0          // [3][128][20] u32 = 30720 (reused as h-staging post-loop)
#define OFF_B    30720      // [3][256][20] u32 = 61440
#define OFF_AROW 92160      // 128 u32
#define OFF_BROW 92672      // 256 u32
#define SMEM_TOTAL 93696

// ======================= PTX helpers =======================
__device__ __forceinline__ uint32_t smem_u32(const void* p) {
    uint32_t a;
    asm("{ .reg .u64 t; cvta.to.shared.u64 t, %1; cvt.u32.u64 %0, t; }" : "=r"(a) : "l"(p));
    return a;
}
#define CPA16(s, g) asm volatile("cp.async.cg.shared.global [%0], [%1], 16;" :: "r"(s), "l"(g))
#define CPC()       asm volatile("cp.async.commit_group;" ::: "memory")
#define CPW(n)      asm volatile("cp.async.wait_group %0;" :: "n"(n) : "memory")

__device__ __forceinline__ void mma_f16(float* d, const uint32_t* a, const uint32_t* b) {
    asm volatile("mma.sync.aligned.m16n8k16.row.col.f32.f16.f16.f32 "
                 "{%0,%1,%2,%3},{%4,%5,%6,%7},{%8,%9},{%0,%1,%2,%3};"
                 : "+f"(d[0]), "+f"(d[1]), "+f"(d[2]), "+f"(d[3])
                 : "r"(a[0]), "r"(a[1]), "r"(a[2]), "r"(a[3]), "r"(b[0]), "r"(b[1]));
}

// ======================= device scratch =======================
__device__ int   g_count[NE];
__device__ int   g_off[NE];
__device__ int   g_tok[NE * N_TOK];
__device__ float g_gate[NE * N_TOK];
__device__ float g_ent;
__device__ float g_imp[NE];

__device__ __align__(16) __half g_xh[(size_t)N_TOK * DIM];
__device__ __align__(16) __half g_w1h[(size_t)NE * HID * DIM];   // [e][n(hid)][k(dim)]
__device__ __align__(16) __half g_w2h[(size_t)NE * DIM * HID];   // [e][n(dim)][k(hid)]
__device__ __align__(16) __half g_hh[(size_t)2 * N_TOK * HID];   // [slot][hid]

// ======================= small kernels =======================
__global__ void zero_kernel() {
    int t = threadIdx.x;
    if (t < NE) { g_count[t] = 0; g_imp[t] = 0.f; }
    if (t == 0) g_ent = 0.f;
}

__global__ void router_kernel(const float* __restrict__ x,
                              const float* __restrict__ rw,
                              const float* __restrict__ rb) {
    __shared__ float s_ent[8];
    __shared__ float s_imp[8][NE];
    int warp = threadIdx.x >> 5;
    int lane = threadIdx.x & 31;
    int t = blockIdx.x * 8 + warp;

    float acc[NE];
#pragma unroll
    for (int e = 0; e < NE; e++) acc[e] = 0.f;
    const float* xr = x + (size_t)t * DIM;
    for (int k = lane; k < DIM; k += 32) {
        float xv = xr[k];
        const float* rwk = rw + k * NE;
#pragma unroll
        for (int e = 0; e < NE; e++) acc[e] += xv * rwk[e];
    }
#pragma unroll
    for (int e = 0; e < NE; e++)
#pragma unroll
        for (int s = 16; s > 0; s >>= 1)
            acc[e] += __shfl_xor_sync(0xffffffff, acc[e], s);

    if (lane == 0) {
        float lg[NE], m = -1e30f;
#pragma unroll
        for (int e = 0; e < NE; e++) { lg[e] = acc[e] + rb[e]; m = fmaxf(m, lg[e]); }
        float p[NE], sum = 0.f;
#pragma unroll
        for (int e = 0; e < NE; e++) { p[e] = expf(lg[e] - m); sum += p[e]; }
        float inv = 1.f / sum, ent = 0.f;
#pragma unroll
        for (int e = 0; e < NE; e++) {
            float pe = p[e] * inv;
            ent -= pe * logf(fmaxf(pe, 1e-8f));
            s_imp[warp][e] = pe;
        }
        s_ent[warp] = ent;
        int e0 = 0;
#pragma unroll
        for (int e = 1; e < NE; e++) if (lg[e] > lg[e0]) e0 = e;
        int e1 = (e0 == 0) ? 1 : 0;
#pragma unroll
        for (int e = 0; e < NE; e++) if (e != e0 && lg[e] > lg[e1]) e1 = e;
        float g0 = 1.f / (1.f + expf(lg[e1] - lg[e0]));
        float g1 = 1.f - g0;
        int p0 = atomicAdd(&g_count[e0], 1);
        g_tok [e0 * N_TOK + p0] = t; g_gate[e0 * N_TOK + p0] = g0;
        int p1 = atomicAdd(&g_count[e1], 1);
        g_tok [e1 * N_TOK + p1] = t; g_gate[e1 * N_TOK + p1] = g1;
    }
    __syncthreads();
    if (threadIdx.x < NE) {
        float se = 0.f;
#pragma unroll
        for (int w = 0; w < 8; w++) se += s_imp[w][threadIdx.x];
        atomicAdd(&g_imp[threadIdx.x], se);
    }
    if (threadIdx.x == 0) {
        float se = 0.f;
#pragma unroll
        for (int w = 0; w < 8; w++) se += s_ent[w];
        atomicAdd(&g_ent, se);
    }
}

__global__ void offsets_kernel() {
    if (threadIdx.x == 0) {
        int s = 0;
#pragma unroll
        for (int e = 0; e < NE; e++) { g_off[e] = s; s += g_count[e]; }
    }
}

__global__ void convert_x_kernel(const float* __restrict__ x) {
    size_t i = ((size_t)blockIdx.x * 256 + threadIdx.x) * 4;
    float4 v = *(const float4*)(x + i);
    uint32_t p0 = (uint32_t)__half_as_ushort(__float2half_rn(v.x))
                | ((uint32_t)__half_as_ushort(__float2half_rn(v.y)) << 16);
    uint32_t p1 = (uint32_t)__half_as_ushort(__float2half_rn(v.z))
                | ((uint32_t)__half_as_ushort(__float2half_rn(v.w)) << 16);
    *(uint2*)(g_xh + i) = make_uint2(p0, p1);
}

// transpose: src [e][R][C] fp32 -> INTERNAL dst [e][C][R] fp16, 8B vector stores.
// which=0 -> g_w1h ; which=1 -> g_w2h   (never pass device globals as host args)
__global__ void transpose_convert_kernel(const float* __restrict__ src,
                                         int which, int R, int C) {
    __shared__ float t[32][33];
    __half* dh = which ? g_w2h : g_w1h;
    int e = blockIdx.z;
    int c0 = blockIdx.x * 32, r0 = blockIdx.y * 32;
    const float* s = src + (size_t)e * R * C;
    int tx = threadIdx.x & 31, ty = threadIdx.x >> 5;
#pragma unroll
    for (int i = ty; i < 32; i += 8)
        t[i][tx] = s[(size_t)(r0 + i) * C + c0 + tx];
    __syncthreads();
    int co = threadIdx.x >> 3;
    int rg = (threadIdx.x & 7) * 4;
    __half h0 = __float2half_rn(t[rg + 0][co]);
    __half h1 = __float2half_rn(t[rg + 1][co]);
    __half h2 = __float2half_rn(t[rg + 2][co]);
    __half h3 = __float2half_rn(t[rg + 3][co]);
    uint2 v;
    v.x = (uint32_t)__half_as_ushort(h0) | ((uint32_t)__half_as_ushort(h1) << 16);
    v.y = (uint32_t)__half_as_ushort(h2) | ((uint32_t)__half_as_ushort(h3) << 16);
    size_t o = (size_t)e * R * C + (size_t)(c0 + co) * R + r0 + rg;
    *(uint2*)(dh + o) = v;
}

// ======================= cp.async stage loader (K-chunk 32 = 64B/row) =======================
__device__ __forceinline__ void load_stage(
    uint32_t abase, uint32_t bbase,
    const __half* __restrict__ Ah, const __half* __restrict__ Bh,
    const uint32_t* __restrict__ arow, const uint32_t* __restrict__ brow,
    int k0, int buf)
{
    int tid = threadIdx.x;
    int row = tid >> 1, hf = tid & 1;

    uint32_t ka = arow[row] + k0 + hf * 16;
    uint32_t da = abase + (uint32_t)buf * (128 * 80) + (uint32_t)row * 80 + hf * 32;
    CPA16(da,      Ah + ka);
    CPA16(da + 16, Ah + ka + 8);

    uint32_t kb0 = brow[row]       + k0 + hf * 16;
    uint32_t kb1 = brow[row + 128] + k0 + hf * 16;
    uint32_t db = bbase + (uint32_t)buf * (256 * 80) + (uint32_t)row * 80 + hf * 32;
    CPA16(db,                 Bh + kb0);
    CPA16(db + 16,            Bh + kb0 + 8);
    CPA16(db + 128 * 80,      Bh + kb1);
    CPA16(db + 128 * 80 + 16, Bh + kb1 + 8);
    CPC();
}

// ======================= GEMM mainloop: CTA 128x256, warp 64x64 =======================
// K-stage 32, 3-buffer cp.async pipeline, ONE __syncthreads per stage.
__device__ __forceinline__ void mma_mainloop(
    char* smc,
    const __half* __restrict__ Ah, const __half* __restrict__ Bh,
    const uint32_t* __restrict__ arow, const uint32_t* __restrict__ brow,
    int S, float (&acc)[4][8][4])
{
    int tid  = threadIdx.x;
    int lane = tid & 31;
    int wid  = tid >> 5;
    int wm   = wid & 1;        // 2 m-groups of 64
    int wn   = wid >> 1;       // 4 n-groups of 64
    int q    = lane & 3;
    int r4   = lane >> 2;

    uint32_t (*A)[128][20] = (uint32_t (*)[128][20])(smc + OFF_A);
    uint32_t (*B)[256][20] = (uint32_t (*)[256][20])(smc + OFF_B);
    uint32_t abase = smem_u32(&A[0][0][0]);
    uint32_t bbase = smem_u32(&B[0][0][0]);

    load_stage(abase, bbase, Ah, Bh, arow, brow, 0,  0);
    load_stage(abase, bbase, Ah, Bh, arow, brow, 32, 1);

    int bu = 0, bnx = 2;
    for (int s = 0; s < S; s++) {
        CPW(1);
        __syncthreads();
        if (s + 2 < S)
            load_stage(abase, bbase, Ah, Bh, arow, brow, (s + 2) * 32, bnx);
        else
            CPC();   // keep group accounting uniform

#pragma unroll
        for (int kc = 0; kc < 2; kc++) {
            int kq = kc * 8 + q;
            uint32_t bhf[8][2];
#pragma unroll
            for (int nt = 0; nt < 8; nt++) {
                int nb = wn * 64 + nt * 8 + r4;
                bhf[nt][0] = B[bu][nb][kq];
                bhf[nt][1] = B[bu][nb][kq + 4];
            }
#pragma unroll
            for (int mt = 0; mt < 4; mt++) {
                int ra = wm * 64 + mt * 16 + r4;
                uint32_t ah[4];
                ah[0] = A[bu][ra][kq];      ah[1] = A[bu][ra + 8][kq];
                ah[2] = A[bu][ra][kq + 4];  ah[3] = A[bu][ra + 8][kq + 4];
#pragma unroll
                for (int nt = 0; nt < 8; nt++)
                    mma_f16(acc[mt][nt], ah, bhf[nt]);
            }
        }
        bu = (bu == 2) ? 0 : bu + 1;
        bnx = (bnx == 2) ? 0 : bnx + 1;
    }
    __syncthreads();   // all compute done before smem reuse
}

// ======================= GEMM1: h = relu(x @ w1 + b1) =======================
__global__ void __launch_bounds__(256)
gemm1_mma(const float* __restrict__ b1) {
    int e = blockIdx.z;
    int ce = g_count[e];
    int m0 = blockIdx.y * 128;
    if (m0 >= ce) return;
    int n0 = blockIdx.x * 256;
    int off = g_off[e];

    extern __shared__ char smc[];
    uint32_t* s_arow = (uint32_t*)(smc + OFF_AROW);
    uint32_t* s_brow = (uint32_t*)(smc + OFF_BROW);

    int tid = threadIdx.x;
    if (tid < 128) {
        int tok = (m0 + tid < ce) ? g_tok[e * N_TOK + m0 + tid] : 0;
        s_arow[tid] = (uint32_t)tok * DIM;
    }
    s_brow[tid] = (uint32_t)(e * HID + n0 + tid) * DIM;
    __syncthreads();

    float acc[4][8][4];
#pragma unroll
    for (int i = 0; i < 4; i++)
#pragma unroll
        for (int j = 0; j < 8; j++)
#pragma unroll
            for (int k = 0; k < 4; k++) acc[i][j][k] = 0.f;

    mma_mainloop(smc, g_xh, g_w1h, s_arow, s_brow, DIM / 32, acc);

    // epilogue: bias + relu -> stage 16x64 fp16 tile in smem -> coalesced 16B stores
    int lane = tid & 31, wid = tid >> 5;
    int wm = wid & 1, wn = wid >> 1;
    int r = lane >> 2, q = lane & 3;
    __half* stg = (__half*)(smc + OFF_A) + (size_t)wid * 1152;  // 16 rows x 72
    const float* brow_b1 = b1 + e * HID + n0 + wn * 64;
    int lr2 = lane >> 1, half2 = lane & 1;

#pragma unroll
    for (int mt = 0; mt < 4; mt++) {
#pragma unroll
        for (int rh = 0; rh < 2; rh++) {
            int lr = r + rh * 8;
#pragma unroll
            for (int nt = 0; nt < 8; nt++) {
                int lc = nt * 8 + 2 * q;
                float f0 = fmaxf(acc[mt][nt][rh * 2 + 0] + brow_b1[lc],     0.f);
                float f1 = fmaxf(acc[mt][nt][rh * 2 + 1] + brow_b1[lc + 1], 0.f);
                uint32_t ph = (uint32_t)__half_as_ushort(__float2half_rn(f0))
                            | ((uint32_t)__half_as_ushort(__float2half_rn(f1)) << 16);
                *(uint32_t*)(stg + lr * 72 + lc) = ph;
            }
        }
        __syncwarp();
        int grow = wm * 64 + mt * 16 + lr2;
        if (m0 + grow < ce) {
            size_t slot = (size_t)(off + m0 + grow);
            __half* dst = g_hh + slot * HID + n0 + wn * 64 + half2 * 32;
            const __half* srcp = stg + lr2 * 72 + half2 * 32;
#pragma unroll
            for (int c = 0; c < 4; c++)
                *(uint4*)(dst + c * 8) = *(const uint4*)(srcp + c * 8);
        }
        __syncwarp();
    }
}

// ======================= GEMM2: out += gate * (h @ w2 + b2) =======================
// Each CTA processes TWO m-tiles sequentially (grid.y halved) so the active CTA
// count (~256) fits in one wave of 2-CTA/SM occupancy — kills wave quantization.
__global__ void __launch_bounds__(256)
gemm2_mma(const float* __restrict__ b2, float* __restrict__ out) {
    int e = blockIdx.z;
    int ce = g_count[e];
    int n0 = blockIdx.x * 256;
    int off = g_off[e];

    extern __shared__ char smc[];
    uint32_t* s_arow = (uint32_t*)(smc + OFF_AROW);
    uint32_t* s_brow = (uint32_t*)(smc + OFF_BROW);

    int tid = threadIdx.x;
    int lane = tid & 31, wid = tid >> 5;
    int wm = wid & 1, wn = wid >> 1;
    int r = lane >> 2, q = lane & 3;

    s_brow[tid] = (uint32_t)(e * DIM + n0 + tid) * HID;

#pragma unroll 1
    for (int mi = 0; mi < 2; mi++) {
        int m0 = (blockIdx.y * 2 + mi) * 128;
        if (m0 >= ce) break;

        __syncthreads();   // brow store (mi=0) / prior tile fully done (mi=1)
        if (tid < 128) {
            int sl = off + m0 + tid;
            if (sl > 2 * N_TOK - 1) sl = 2 * N_TOK - 1;
            s_arow[tid] = (uint32_t)sl * HID;
        }
        __syncthreads();

        float acc[4][8][4];
#pragma unroll
        for (int i = 0; i < 4; i++)
#pragma unroll
            for (int j = 0; j < 8; j++)
#pragma unroll
                for (int k = 0; k < 4; k++) acc[i][j][k] = 0.f;

        mma_mainloop(smc, g_hh, g_w2h, s_arow, s_brow, HID / 32, acc);

        // epilogue: gate-weighted atomic add
#pragma unroll
        for (int mt = 0; mt < 4; mt++) {
#pragma unroll
            for (int rh = 0; rh < 2; rh++) {
                int row = wm * 64 + mt * 16 + r + rh * 8;
                if (m0 + row >= ce) continue;
                int slot2 = e * N_TOK + m0 + row;
                int tok = g_tok[slot2];
                float gw = g_gate[slot2];
                float* ob = out + (size_t)tok * DIM;
#pragma unroll
                for (int nt = 0; nt < 8; nt++) {
                    int col = n0 + wn * 64 + nt * 8 + 2 * q;
                    float f0 = acc[mt][nt][rh * 2 + 0] + b2[e * DIM + col];
                    float f1 = acc[mt][nt][rh * 2 + 1] + b2[e * DIM + col + 1];
                    atomicAdd(ob + col,     gw * f0);
                    atomicAdd(ob + col + 1, gw * f1);
                }
            }
        }
    }
}

// ======================= aux =======================
__global__ void aux_kernel(float* __restrict__ out, int out_size) {
    if (threadIdx.x == 0 && out_size >= N_TOK * DIM + 2) {
        float ent = g_ent / (float)N_TOK;
        float lb = 0.f;
#pragma unroll
        for (int e = 0; e < NE; e++) {
            float d = g_imp[e] / (float)N_TOK - 1.f / (float)NE;
            lb += d * d;
        }
        lb /= (float)NE;
        out[N_TOK * DIM]     = ent;
        out[N_TOK * DIM + 1] = lb;
    }
}

// ======================= launch (single stream) =======================
extern "C" void kernel_launch(void* const* d_in, const int* in_sizes, int n_in,
                              void* d_out, int out_size) {
    const float* x  = (const float*)d_in[0];
    const float* rw = (const float*)d_in[1];
    const float* rb = (const float*)d_in[2];
    const float* w1 = (const float*)d_in[3];
    const float* b1 = (const float*)d_in[4];
    const float* w2 = (const float*)d_in[5];
    const float* b2 = (const float*)d_in[6];
    float* out = (float*)d_out;

    cudaFuncSetAttribute(gemm1_mma, cudaFuncAttributeMaxDynamicSharedMemorySize, SMEM_TOTAL);
    cudaFuncSetAttribute(gemm2_mma, cudaFuncAttributeMaxDynamicSharedMemorySize, SMEM_TOTAL);

    cudaMemsetAsync(d_out, 0, (size_t)out_size * sizeof(float), 0);
    zero_kernel<<<1, 32>>>();
    router_kernel<<<N_TOK / 8, 256>>>(x, rw, rb);
    offsets_kernel<<<1, 1>>>();
    convert_x_kernel<<<(N_TOK * DIM) / 1024, 256>>>(x);
    {
        dim3 g(HID / 32, DIM / 32, NE);
        transpose_convert_kernel<<<g, 256>>>(w1, 0, DIM, HID);
    }
    {
        dim3 g(DIM / 32, HID / 32, NE);
        transpose_convert_kernel<<<g, 256>>>(w2, 1, HID, DIM);
    }

    {
        dim3 g(HID / 256, N_TOK / 128, NE);
        gemm1_mma<<<g, 256, SMEM_TOTAL>>>(b1);
    }
    {
        dim3 g(DIM / 256, N_TOK / 256, NE);   // grid.y halved: 2 m-tiles per CTA
        gemm2_mma<<<g, 256, SMEM_TOTAL>>>(b2, out);
    }
    aux_kernel<<<1, 1>>>(out, out_size);
}